// round 7
// baseline (speedup 1.0000x reference)
#include <cuda_runtime.h>
#include <cuda_bf16.h>
#include <math.h>
#include <stdint.h>

#define Bv 16384
#define Dv 256
#define Ev 8
#define NBv 17          // 136 blocks, one wave
#define MT 128          // tokens per tile

__device__ int   g_count[Ev];
__device__ int   g_tok[Ev][Bv];
__device__ float g_w[Ev][Bv];
// pre-swizzled bf16 weight images: W1 [e][half][hi/lo] 32KB each (1MB),
// then Wp [e][hi/lo] 32KB each (0.5MB)
__device__ uint4 g_img4[1572864 / 16];

__device__ __forceinline__ uint32_t smem_u32(const void* p) {
    uint32_t a;
    asm("{ .reg .u64 t; cvta.to.shared.u64 t, %1; cvt.u32.u64 %0, t; }"
        : "=r"(a) : "l"(p));
    return a;
}
__device__ __forceinline__ uint32_t packbf(float even, float odd) {
    uint32_t r;
    asm("cvt.rn.bf16x2.f32 %0, %1, %2;" : "=r"(r) : "f"(odd), "f"(even));
    return r;
}
__device__ __forceinline__ float blo(float v) {
    return v - __bfloat162float(__float2bfloat16(v));
}
__device__ __forceinline__ void ldsm4(uint32_t addr, uint32_t* r) {
    asm volatile("ldmatrix.sync.aligned.m8n8.x4.shared.b16 {%0,%1,%2,%3}, [%4];"
        : "=r"(r[0]), "=r"(r[1]), "=r"(r[2]), "=r"(r[3]) : "r"(addr));
}
__device__ __forceinline__ void mma_bf(float* d, const uint32_t* a,
                                       uint32_t b0, uint32_t b1) {
    asm volatile("mma.sync.aligned.m16n8k16.row.col.f32.bf16.bf16.f32 "
        "{%0,%1,%2,%3}, {%4,%5,%6,%7}, {%8,%9}, {%0,%1,%2,%3};"
        : "+f"(d[0]), "+f"(d[1]), "+f"(d[2]), "+f"(d[3])
        : "r"(a[0]), "r"(a[1]), "r"(a[2]), "r"(a[3]), "r"(b0), "r"(b1));
}

__global__ void k_zero() {
    if (threadIdx.x < Ev) g_count[threadIdx.x] = 0;
}

// build transposed, bf16 hi/lo split, pre-swizzled weight images
__global__ void __launch_bounds__(256) k_prep(const float* __restrict__ W1,
                                              const float* __restrict__ Wp) {
    int e = blockIdx.x;
    unsigned char* img = (unsigned char*)g_img4;
    // W1[e][d][h] -> row h, col d (K-halves of 128)
    for (int i = threadIdx.x; i < 32768; i += 256) {
        int d = i >> 7, h = i & 127;
        float v = W1[e * 32768 + i];
        int half = d >> 7, dl = d & 127;
        uint32_t off = (uint32_t)h * 256 + (((uint32_t)dl * 2) ^ ((h & 7) * 16));
        uint32_t hb = (uint32_t)((e * 2 + half) * 2) * 32768u;
        *(__nv_bfloat16*)(img + hb + off)          = __float2bfloat16(v);
        *(__nv_bfloat16*)(img + hb + 32768u + off) = __float2bfloat16(blo(v));
    }
    // Wp[e][h][k] -> row k, col h
    for (int i = threadIdx.x; i < 16384; i += 256) {
        int k = i & 127, h = i >> 7;
        float v = Wp[e * 16384 + i];
        uint32_t off = (uint32_t)k * 256 + (((uint32_t)h * 2) ^ ((k & 7) * 16));
        uint32_t base = 1048576u + (uint32_t)(e * 2) * 32768u;
        *(__nv_bfloat16*)(img + base + off)          = __float2bfloat16(v);
        *(__nv_bfloat16*)(img + base + 32768u + off) = __float2bfloat16(blo(v));
    }
}

__global__ void __launch_bounds__(256) k_gate(const float* __restrict__ feat,
                                              const float* __restrict__ Wg,
                                              float* __restrict__ out) {
    __shared__ float WgT[Ev * 256];
    for (int i = threadIdx.x; i < Dv * Ev; i += 256)
        WgT[(i & 7) * 256 + (i >> 3)] = Wg[i];
    __syncthreads();
    int l = threadIdx.x & 31;
    int tok = blockIdx.x * 8 + (threadIdx.x >> 5);
    if (l == 0) out[tok] = 0.f;
    const float* x = feat + (size_t)tok * Dv;
    float acc[Ev];
#pragma unroll
    for (int e = 0; e < Ev; e++) acc[e] = 0.f;
#pragma unroll
    for (int d0 = 0; d0 < Dv; d0 += 128) {
        float4 x4 = *(const float4*)(x + d0 + l * 4);
#pragma unroll
        for (int e = 0; e < Ev; e++) {
            const float* wr = WgT + e * 256 + d0 + l * 4;
            acc[e] += x4.x * wr[0] + x4.y * wr[1] + x4.z * wr[2] + x4.w * wr[3];
        }
    }
#pragma unroll
    for (int e = 0; e < Ev; e++)
#pragma unroll
        for (int off = 16; off; off >>= 1)
            acc[e] += __shfl_down_sync(0xffffffffu, acc[e], off);
    if (l == 0) {
        float m = acc[0];
#pragma unroll
        for (int e = 1; e < Ev; e++) m = fmaxf(m, acc[e]);
        float g[Ev], sum = 0.f;
#pragma unroll
        for (int e = 0; e < Ev; e++) { g[e] = expf(acc[e] - m); sum += g[e]; }
        float inv = 1.f / sum;
#pragma unroll
        for (int e = 0; e < Ev; e++) g[e] *= inv;
        int i0 = 0;
#pragma unroll
        for (int e = 1; e < Ev; e++) if (g[e] > g[i0]) i0 = e;
        int i1 = -1;
#pragma unroll
        for (int e = 0; e < Ev; e++) {
            if (e == i0) continue;
            if (i1 < 0 || g[e] > g[i1]) i1 = e;
        }
        float denom = g[i0] + g[i1] + 1e-10f;
        int r0 = atomicAdd(&g_count[i0], 1);
        g_tok[i0][r0] = tok; g_w[i0][r0] = g[i0] / denom;
        int r1 = atomicAdd(&g_count[i1], 1);
        g_tok[i1][r1] = tok; g_w[i1][r1] = g[i1] / denom;
    }
}

// smem: Ahi 0 (32K), Alo 32768, W1h_hi 65536, W1h_lo 98304,
//       Wp_hi 131072, Wp_lo 163840, tk 196608, wt 197120,
//       b1 197632, bp 198144, Wo 198656 -> total 199168
#define OFF_AHI 0
#define OFF_ALO 32768
#define OFF_WH  65536
#define OFF_WL  98304
#define OFF_PH  131072
#define OFF_PL  163840
#define SMEM_BYTES 199168

__global__ void __launch_bounds__(256, 1) k_expert(
    const float* __restrict__ feat,
    const float* __restrict__ b1g, const float* __restrict__ bpg,
    const float* __restrict__ mix_logit,
    const float* __restrict__ Wog, const float* __restrict__ bog,
    float* __restrict__ out)
{
    extern __shared__ __align__(1024) char smb[];
    int*   tk   = (int*)(smb + 196608);
    float* wt   = (float*)(smb + 197120);
    float* b1_s = (float*)(smb + 197632);
    float* bp_s = (float*)(smb + 198144);
    float* Wo_s = (float*)(smb + 198656);

    const int e    = blockIdx.x & 7;
    const int j    = blockIdx.x >> 3;
    const int tid  = threadIdx.x;
    const int warp = tid >> 5;
    const int lane = tid & 31;
    const int li   = lane & 3;
    const int lg   = lane >> 2;
    const uint32_t sb = smem_u32(smb);

    // stage Wp images (resident whole kernel) + biases
    {
        const uint4* s = g_img4 + 65536 + (size_t)(e * 2) * 2048;
        uint4* dH = (uint4*)(smb + OFF_PH);
        uint4* dL = (uint4*)(smb + OFF_PL);
        for (int u = tid; u < 2048; u += 256) { dH[u] = s[u]; dL[u] = s[u + 2048]; }
    }
    if (tid < 128) {
        b1_s[tid] = b1g[e * 128 + tid];
        bp_s[tid] = bpg[e * 128 + tid];
        Wo_s[tid] = Wog[e * 128 + tid];
    }
    const float mix  = 1.f / (1.f + expf(-mix_logit[e]));
    const float omix = 1.f - mix;
    const float boe  = bog[e];
    const int   n    = g_count[e];

    // fragment addressing (swizzle: byte = row*256 + (kbyte ^ ((row&7)*16)))
    const int matA = lane >> 3;
    const int arow = warp * 16 + (matA & 1) * 8 + (lane & 7);
    const uint32_t a_koff = (uint32_t)(matA >> 1) * 16;
    const uint32_t a_sw   = (uint32_t)(arow & 7) * 16;
    const uint32_t a_rowb = (uint32_t)arow * 256;
    const int jt = matA >> 1, kc = matA & 1;   // B-fragment roles
    const int brow_lo = jt * 8 + (lane & 7);   // + ntp*16
    const uint32_t b_koff = (uint32_t)kc * 16;

    for (int tile = j; tile * MT < n; tile += NBv) {
        const int base = tile * MT;
        __syncthreads();                         // protect tk/wt + smem reuse
        if (tid < 128) {
            int idx = min(base + tid, n - 1);
            tk[tid] = g_tok[e][idx];
            wt[tid] = g_w[e][idx];
        }

        float D1[16][4];
#pragma unroll
        for (int t = 0; t < 16; t++)
#pragma unroll
            for (int q = 0; q < 4; q++) D1[t][q] = 0.f;

        // ===== GEMM1: D1 = x @ W1, two K-halves, 3-pass bf16 split =====
        for (int half = 0; half < 2; half++) {
            __syncthreads();
            // stage A half (gather + split + swizzle)
            for (int u = tid; u < 4096; u += 256) {
                int ts = u >> 5, d = (u & 31) * 4;
                float4 x4 = *(const float4*)(feat + (size_t)tk[ts] * Dv
                                             + half * 128 + d);
                uint32_t off = (uint32_t)ts * 256
                             + (((uint32_t)d * 2) ^ ((ts & 7) * 16));
                *(uint2*)(smb + OFF_AHI + off) =
                    make_uint2(packbf(x4.x, x4.y), packbf(x4.z, x4.w));
                *(uint2*)(smb + OFF_ALO + off) =
                    make_uint2(packbf(blo(x4.x), blo(x4.y)),
                               packbf(blo(x4.z), blo(x4.w)));
            }
            // stage W1 half images
            {
                const uint4* s = g_img4 + (size_t)((e * 2 + half) * 2) * 2048;
                uint4* dH = (uint4*)(smb + OFF_WH);
                uint4* dL = (uint4*)(smb + OFF_WL);
                for (int u = tid; u < 2048; u += 256) {
                    dH[u] = s[u]; dL[u] = s[u + 2048];
                }
            }
            __syncthreads();

            for (int ks = 0; ks < 8; ks++) {
                uint32_t akx = (((uint32_t)ks * 32 + a_koff) ^ a_sw) + a_rowb;
                uint32_t ah[4], al[4];
                ldsm4(sb + OFF_AHI + akx, ah);
                ldsm4(sb + OFF_ALO + akx, al);
#pragma unroll
                for (int ntp = 0; ntp < 8; ntp++) {
                    int brow = ntp * 16 + brow_lo;
                    uint32_t bkx = (((uint32_t)ks * 32 + b_koff)
                                    ^ ((brow & 7) * 16)) + (uint32_t)brow * 256;
                    uint32_t bh[4], bl[4];
                    ldsm4(sb + OFF_WH + bkx, bh);
                    ldsm4(sb + OFF_WL + bkx, bl);
                    mma_bf(D1[2 * ntp],     ah, bh[0], bh[1]);
                    mma_bf(D1[2 * ntp + 1], ah, bh[2], bh[3]);
                    mma_bf(D1[2 * ntp],     ah, bl[0], bl[1]);
                    mma_bf(D1[2 * ntp + 1], ah, bl[2], bl[3]);
                    mma_bf(D1[2 * ntp],     al, bh[0], bh[1]);
                    mma_bf(D1[2 * ntp + 1], al, bh[2], bh[3]);
                }
            }
        }

        // ===== epilogue 1: relu + b1; pack GEMM2 A fragments in regs =====
        float s1m = 0.f, s1m8 = 0.f;
        uint32_t A2h[8][4], A2l[8][4];
#pragma unroll
        for (int nt = 0; nt < 16; nt++) {
            float2 b1v = *(float2*)(b1_s + nt * 8 + li * 2);
            float2 wov = *(float2*)(Wo_s + nt * 8 + li * 2);
            float c0 = fmaxf(D1[nt][0] + b1v.x, 0.f);
            float c1 = fmaxf(D1[nt][1] + b1v.y, 0.f);
            float c2 = fmaxf(D1[nt][2] + b1v.x, 0.f);
            float c3 = fmaxf(D1[nt][3] + b1v.y, 0.f);
            s1m  += c0 * wov.x + c1 * wov.y;
            s1m8 += c2 * wov.x + c3 * wov.y;
            int jj = nt >> 1, sl = (nt & 1) * 2;
            A2h[jj][sl]     = packbf(c0, c1);
            A2h[jj][sl + 1] = packbf(c2, c3);
            A2l[jj][sl]     = packbf(blo(c0), blo(c1));
            A2l[jj][sl + 1] = packbf(blo(c2), blo(c3));
        }

        // ===== GEMM2: D2 = core @ Wp (A in regs, B = resident Wp) =====
        float D2[16][4];
#pragma unroll
        for (int t = 0; t < 16; t++)
#pragma unroll
            for (int q = 0; q < 4; q++) D2[t][q] = 0.f;
#pragma unroll
        for (int ks = 0; ks < 8; ks++) {
#pragma unroll
            for (int ntp = 0; ntp < 8; ntp++) {
                int brow = ntp * 16 + brow_lo;
                uint32_t bkx = (((uint32_t)ks * 32 + b_koff)
                                ^ ((brow & 7) * 16)) + (uint32_t)brow * 256;
                uint32_t bh[4], bl[4];
                ldsm4(sb + OFF_PH + bkx, bh);
                ldsm4(sb + OFF_PL + bkx, bl);
                mma_bf(D2[2 * ntp],     A2h[ks], bh[0], bh[1]);
                mma_bf(D2[2 * ntp + 1], A2h[ks], bh[2], bh[3]);
                mma_bf(D2[2 * ntp],     A2h[ks], bl[0], bl[1]);
                mma_bf(D2[2 * ntp + 1], A2h[ks], bl[2], bl[3]);
                mma_bf(D2[2 * ntp],     A2l[ks], bh[0], bh[1]);
                mma_bf(D2[2 * ntp + 1], A2l[ks], bh[2], bh[3]);
            }
        }

        // ===== epilogue 2: tanh + mix + Wo dot + reduce + atomicAdd =====
        float pm = 0.f, pm8 = 0.f;
#pragma unroll
        for (int nt = 0; nt < 16; nt++) {
            float2 bpv = *(float2*)(bp_s + nt * 8 + li * 2);
            float2 wov = *(float2*)(Wo_s + nt * 8 + li * 2);
            pm  += tanhf(D2[nt][0] + bpv.x) * wov.x
                 + tanhf(D2[nt][1] + bpv.y) * wov.y;
            pm8 += tanhf(D2[nt][2] + bpv.x) * wov.x
                 + tanhf(D2[nt][3] + bpv.y) * wov.y;
        }
        float vm  = omix * s1m  + mix * pm;
        float vm8 = omix * s1m8 + mix * pm8;
        vm  += __shfl_xor_sync(0xffffffffu, vm, 1);
        vm  += __shfl_xor_sync(0xffffffffu, vm, 2);
        vm8 += __shfl_xor_sync(0xffffffffu, vm8, 1);
        vm8 += __shfl_xor_sync(0xffffffffu, vm8, 2);
        if (li == 0) {
            int mr = warp * 16 + lg;
            if (base + mr < n)
                atomicAdd(&out[tk[mr]], wt[mr] * (vm + boe));
            if (base + mr + 8 < n)
                atomicAdd(&out[tk[mr + 8]], wt[mr + 8] * (vm8 + boe));
        }
    }
}

extern "C" void kernel_launch(void* const* d_in, const int* in_sizes, int n_in,
                              void* d_out, int out_size) {
    const float* feat      = (const float*)d_in[0];
    const float* Wg        = (const float*)d_in[1];
    const float* W1        = (const float*)d_in[2];
    const float* b1        = (const float*)d_in[3];
    const float* Wp        = (const float*)d_in[4];
    const float* bp        = (const float*)d_in[5];
    const float* mix_logit = (const float*)d_in[6];
    const float* Wo        = (const float*)d_in[7];
    const float* bo        = (const float*)d_in[8];
    float* out = (float*)d_out;

    cudaFuncSetAttribute(k_expert, cudaFuncAttributeMaxDynamicSharedMemorySize,
                         SMEM_BYTES);
    k_zero<<<1, 32>>>();
    k_prep<<<Ev, 256>>>(W1, Wp);
    k_gate<<<Bv / 8, 256>>>(feat, Wg, out);
    k_expert<<<NBv * Ev, 256, SMEM_BYTES>>>(feat, b1, bp, mix_logit, Wo, bo, out);
}

// round 8
// speedup vs baseline: 2.2178x; 2.2178x over previous
#include <cuda_runtime.h>
#include <cuda_bf16.h>
#include <math.h>
#include <stdint.h>

#define Bv 16384
#define Dv 256
#define Ev 8
#define NBv 17          // 136 blocks, one wave
#define MT 128          // tokens per tile

__device__ int   g_count[Ev];
__device__ int   g_tok[Ev][Bv];
__device__ float g_w[Ev][Bv];
// pre-swizzled bf16 weight images: W1 [e][half][hi/lo] 32KB each (1MB),
// then Wp [e][hi/lo] 32KB each (0.5MB)
__device__ uint4 g_img4[1572864 / 16];

__device__ __forceinline__ uint32_t smem_u32(const void* p) {
    uint32_t a;
    asm("{ .reg .u64 t; cvta.to.shared.u64 t, %1; cvt.u32.u64 %0, t; }"
        : "=r"(a) : "l"(p));
    return a;
}
__device__ __forceinline__ uint32_t packbf(float even, float odd) {
    uint32_t r;
    asm("cvt.rn.bf16x2.f32 %0, %1, %2;" : "=r"(r) : "f"(odd), "f"(even));
    return r;
}
__device__ __forceinline__ float blo(float v) {
    return v - __bfloat162float(__float2bfloat16(v));
}
__device__ __forceinline__ void ldsm4(uint32_t addr, uint32_t* r) {
    asm volatile("ldmatrix.sync.aligned.m8n8.x4.shared.b16 {%0,%1,%2,%3}, [%4];"
        : "=r"(r[0]), "=r"(r[1]), "=r"(r[2]), "=r"(r[3]) : "r"(addr));
}
__device__ __forceinline__ void mma_bf(float* d, const uint32_t* a,
                                       uint32_t b0, uint32_t b1) {
    asm volatile("mma.sync.aligned.m16n8k16.row.col.f32.bf16.bf16.f32 "
        "{%0,%1,%2,%3}, {%4,%5,%6,%7}, {%8,%9}, {%0,%1,%2,%3};"
        : "+f"(d[0]), "+f"(d[1]), "+f"(d[2]), "+f"(d[3])
        : "r"(a[0]), "r"(a[1]), "r"(a[2]), "r"(a[3]), "r"(b0), "r"(b1));
}

// ---- k_prep: parallel weight-image build (coalesced 4B stores) + zero ----
__global__ void __launch_bounds__(256) k_prep(const float* __restrict__ W1,
                                              const float* __restrict__ Wp) {
    const int e = blockIdx.x >> 4;        // 16 blocks per expert
    const int p = blockIdx.x & 15;
    unsigned char* img = (unsigned char*)g_img4;
    if (blockIdx.x == 0 && threadIdx.x < Ev) g_count[threadIdx.x] = 0;

    // W1[e][d][h] -> image row h, cols d (two K-halves of 128).
    // item i: h = i >> 7, d2 = i & 127 (pair dg = 2*d2) -> 4-byte store.
    for (int q = 0; q < 4; q++) {
        int i = (p * 4 + q) * 256 + threadIdx.x;       // 0..16383
        int h = i >> 7, d2 = i & 127;
        int dg = d2 * 2;
        float v0 = W1[e * 32768 + dg * 128 + h];
        float v1 = W1[e * 32768 + (dg + 1) * 128 + h];
        int half = dg >> 7, dl = dg & 127;
        uint32_t off = (uint32_t)h * 256 + (((uint32_t)dl * 2) ^ ((h & 7) * 16));
        uint32_t hb = (uint32_t)((e * 2 + half) * 2) * 32768u;
        *(uint32_t*)(img + hb + off)          = packbf(v0, v1);
        *(uint32_t*)(img + hb + 32768u + off) = packbf(blo(v0), blo(v1));
    }
    // Wp[e][h][k] -> image row k, cols h. item i: k = i >> 6, h2 = i & 63.
    for (int q = 0; q < 2; q++) {
        int i = (p * 2 + q) * 256 + threadIdx.x;       // 0..8191
        int k = i >> 6, h2 = i & 63;
        int hg = h2 * 2;
        float v0 = Wp[e * 16384 + hg * 128 + k];
        float v1 = Wp[e * 16384 + (hg + 1) * 128 + k];
        uint32_t off = (uint32_t)k * 256 + (((uint32_t)hg * 2) ^ ((k & 7) * 16));
        uint32_t base = 1048576u + (uint32_t)(e * 2) * 32768u;
        *(uint32_t*)(img + base + off)          = packbf(v0, v1);
        *(uint32_t*)(img + base + 32768u + off) = packbf(blo(v0), blo(v1));
    }
}

__global__ void __launch_bounds__(256) k_gate(const float* __restrict__ feat,
                                              const float* __restrict__ Wg,
                                              float* __restrict__ out) {
    __shared__ float WgT[Ev * 256];
    for (int i = threadIdx.x; i < Dv * Ev; i += 256)
        WgT[(i & 7) * 256 + (i >> 3)] = Wg[i];
    __syncthreads();
    int l = threadIdx.x & 31;
    int tok = blockIdx.x * 8 + (threadIdx.x >> 5);
    if (l == 0) out[tok] = 0.f;
    const float* x = feat + (size_t)tok * Dv;
    float acc[Ev];
#pragma unroll
    for (int e = 0; e < Ev; e++) acc[e] = 0.f;
#pragma unroll
    for (int d0 = 0; d0 < Dv; d0 += 128) {
        float4 x4 = *(const float4*)(x + d0 + l * 4);
#pragma unroll
        for (int e = 0; e < Ev; e++) {
            const float* wr = WgT + e * 256 + d0 + l * 4;
            acc[e] += x4.x * wr[0] + x4.y * wr[1] + x4.z * wr[2] + x4.w * wr[3];
        }
    }
#pragma unroll
    for (int e = 0; e < Ev; e++)
#pragma unroll
        for (int off = 16; off; off >>= 1)
            acc[e] += __shfl_down_sync(0xffffffffu, acc[e], off);
    if (l == 0) {
        float m = acc[0];
#pragma unroll
        for (int e = 1; e < Ev; e++) m = fmaxf(m, acc[e]);
        float g[Ev], sum = 0.f;
#pragma unroll
        for (int e = 0; e < Ev; e++) { g[e] = expf(acc[e] - m); sum += g[e]; }
        float inv = 1.f / sum;
#pragma unroll
        for (int e = 0; e < Ev; e++) g[e] *= inv;
        int i0 = 0;
#pragma unroll
        for (int e = 1; e < Ev; e++) if (g[e] > g[i0]) i0 = e;
        int i1 = -1;
#pragma unroll
        for (int e = 0; e < Ev; e++) {
            if (e == i0) continue;
            if (i1 < 0 || g[e] > g[i1]) i1 = e;
        }
        float denom = g[i0] + g[i1] + 1e-10f;
        int r0 = atomicAdd(&g_count[i0], 1);
        g_tok[i0][r0] = tok; g_w[i0][r0] = g[i0] / denom;
        int r1 = atomicAdd(&g_count[i1], 1);
        g_tok[i1][r1] = tok; g_w[i1][r1] = g[i1] / denom;
    }
}

// smem: Ahi 0 (32K), Alo 32768, W1h_hi 65536, W1h_lo 98304,
//       Wp_hi 131072, Wp_lo 163840, tk 196608, wt 197120,
//       b1 197632, bp 198144, Wo 198656 -> total 199168
#define OFF_AHI 0
#define OFF_ALO 32768
#define OFF_WH  65536
#define OFF_WL  98304
#define OFF_PH  131072
#define OFF_PL  163840
#define SMEM_BYTES 199168

__global__ void __launch_bounds__(256, 1) k_expert(
    const float* __restrict__ feat,
    const float* __restrict__ b1g, const float* __restrict__ bpg,
    const float* __restrict__ mix_logit,
    const float* __restrict__ Wog, const float* __restrict__ bog,
    float* __restrict__ out)
{
    extern __shared__ __align__(1024) char smb[];
    int*   tk   = (int*)(smb + 196608);
    float* wt   = (float*)(smb + 197120);
    float* b1_s = (float*)(smb + 197632);
    float* bp_s = (float*)(smb + 198144);
    float* Wo_s = (float*)(smb + 198656);

    const int e    = blockIdx.x & 7;
    const int j    = blockIdx.x >> 3;
    const int tid  = threadIdx.x;
    const int warp = tid >> 5;
    const int lane = tid & 31;
    const int li   = lane & 3;
    const int lg   = lane >> 2;
    const uint32_t sb = smem_u32(smb);

    // stage Wp images (resident whole kernel) + biases
    {
        const uint4* s = g_img4 + 65536 + (size_t)(e * 2) * 2048;
        uint4* dH = (uint4*)(smb + OFF_PH);
        uint4* dL = (uint4*)(smb + OFF_PL);
        for (int u = tid; u < 2048; u += 256) { dH[u] = s[u]; dL[u] = s[u + 2048]; }
    }
    if (tid < 128) {
        b1_s[tid] = b1g[e * 128 + tid];
        bp_s[tid] = bpg[e * 128 + tid];
        Wo_s[tid] = Wog[e * 128 + tid];
    }
    const float mix  = 1.f / (1.f + expf(-mix_logit[e]));
    const float omix = 1.f - mix;
    const float boe  = bog[e];
    const int   n    = g_count[e];

    // fragment addressing (swizzle: byte = row*256 + (kbyte ^ ((row&7)*16)))
    const int matA = lane >> 3;
    const int arow = warp * 16 + (matA & 1) * 8 + (lane & 7);
    const uint32_t a_koff = (uint32_t)(matA >> 1) * 16;
    const uint32_t a_sw   = (uint32_t)(arow & 7) * 16;
    const uint32_t a_rowb = (uint32_t)arow * 256;
    const int jt = matA >> 1, kc = matA & 1;   // B-fragment roles
    const int brow_lo = jt * 8 + (lane & 7);   // + ntp*16
    const uint32_t b_koff = (uint32_t)kc * 16;

    for (int tile = j; tile * MT < n; tile += NBv) {
        const int base = tile * MT;
        __syncthreads();                         // protect tk/wt + smem reuse
        if (tid < 128) {
            int idx = min(base + tid, n - 1);
            tk[tid] = g_tok[e][idx];
            wt[tid] = g_w[e][idx];
        }

        float D1[16][4];
#pragma unroll
        for (int t = 0; t < 16; t++)
#pragma unroll
            for (int q = 0; q < 4; q++) D1[t][q] = 0.f;

        // ===== GEMM1: D1 = x @ W1, two K-halves, 3-pass bf16 split =====
        for (int half = 0; half < 2; half++) {
            __syncthreads();
            // stage A half (gather + split + swizzle)
            for (int u = tid; u < 4096; u += 256) {
                int ts = u >> 5, d = (u & 31) * 4;
                float4 x4 = *(const float4*)(feat + (size_t)tk[ts] * Dv
                                             + half * 128 + d);
                uint32_t off = (uint32_t)ts * 256
                             + (((uint32_t)d * 2) ^ ((ts & 7) * 16));
                *(uint2*)(smb + OFF_AHI + off) =
                    make_uint2(packbf(x4.x, x4.y), packbf(x4.z, x4.w));
                *(uint2*)(smb + OFF_ALO + off) =
                    make_uint2(packbf(blo(x4.x), blo(x4.y)),
                               packbf(blo(x4.z), blo(x4.w)));
            }
            // stage W1 half images
            {
                const uint4* s = g_img4 + (size_t)((e * 2 + half) * 2) * 2048;
                uint4* dH = (uint4*)(smb + OFF_WH);
                uint4* dL = (uint4*)(smb + OFF_WL);
                for (int u = tid; u < 2048; u += 256) {
                    dH[u] = s[u]; dL[u] = s[u + 2048];
                }
            }
            __syncthreads();

            for (int ks = 0; ks < 8; ks++) {
                uint32_t akx = (((uint32_t)ks * 32 + a_koff) ^ a_sw) + a_rowb;
                uint32_t ah[4], al[4];
                ldsm4(sb + OFF_AHI + akx, ah);
                ldsm4(sb + OFF_ALO + akx, al);
#pragma unroll
                for (int ntp = 0; ntp < 8; ntp++) {
                    int brow = ntp * 16 + brow_lo;
                    uint32_t bkx = (((uint32_t)ks * 32 + b_koff)
                                    ^ ((brow & 7) * 16)) + (uint32_t)brow * 256;
                    uint32_t bh[4], bl[4];
                    ldsm4(sb + OFF_WH + bkx, bh);
                    ldsm4(sb + OFF_WL + bkx, bl);
                    mma_bf(D1[2 * ntp],     ah, bh[0], bh[1]);
                    mma_bf(D1[2 * ntp + 1], ah, bh[2], bh[3]);
                    mma_bf(D1[2 * ntp],     ah, bl[0], bl[1]);
                    mma_bf(D1[2 * ntp + 1], ah, bl[2], bl[3]);
                    mma_bf(D1[2 * ntp],     al, bh[0], bh[1]);
                    mma_bf(D1[2 * ntp + 1], al, bh[2], bh[3]);
                }
            }
        }

        // ===== epilogue 1: relu + b1; pack GEMM2 A fragments in regs =====
        float s1m = 0.f, s1m8 = 0.f;
        uint32_t A2h[8][4], A2l[8][4];
#pragma unroll
        for (int nt = 0; nt < 16; nt++) {
            float2 b1v = *(float2*)(b1_s + nt * 8 + li * 2);
            float2 wov = *(float2*)(Wo_s + nt * 8 + li * 2);
            float c0 = fmaxf(D1[nt][0] + b1v.x, 0.f);
            float c1 = fmaxf(D1[nt][1] + b1v.y, 0.f);
            float c2 = fmaxf(D1[nt][2] + b1v.x, 0.f);
            float c3 = fmaxf(D1[nt][3] + b1v.y, 0.f);
            s1m  += c0 * wov.x + c1 * wov.y;
            s1m8 += c2 * wov.x + c3 * wov.y;
            int jj = nt >> 1, sl = (nt & 1) * 2;
            A2h[jj][sl]     = packbf(c0, c1);
            A2h[jj][sl + 1] = packbf(c2, c3);
            A2l[jj][sl]     = packbf(blo(c0), blo(c1));
            A2l[jj][sl + 1] = packbf(blo(c2), blo(c3));
        }

        // ===== GEMM2: D2 = core @ Wp (A in regs, B = resident Wp) =====
        float D2[16][4];
#pragma unroll
        for (int t = 0; t < 16; t++)
#pragma unroll
            for (int q = 0; q < 4; q++) D2[t][q] = 0.f;
#pragma unroll
        for (int ks = 0; ks < 8; ks++) {
#pragma unroll
            for (int ntp = 0; ntp < 8; ntp++) {
                int brow = ntp * 16 + brow_lo;
                uint32_t bkx = (((uint32_t)ks * 32 + b_koff)
                                ^ ((brow & 7) * 16)) + (uint32_t)brow * 256;
                uint32_t bh[4], bl[4];
                ldsm4(sb + OFF_PH + bkx, bh);
                ldsm4(sb + OFF_PL + bkx, bl);
                mma_bf(D2[2 * ntp],     A2h[ks], bh[0], bh[1]);
                mma_bf(D2[2 * ntp + 1], A2h[ks], bh[2], bh[3]);
                mma_bf(D2[2 * ntp],     A2h[ks], bl[0], bl[1]);
                mma_bf(D2[2 * ntp + 1], A2h[ks], bl[2], bl[3]);
                mma_bf(D2[2 * ntp],     A2l[ks], bh[0], bh[1]);
                mma_bf(D2[2 * ntp + 1], A2l[ks], bh[2], bh[3]);
            }
        }

        // ===== epilogue 2: tanh + mix + Wo dot + reduce + atomicAdd =====
        float pm = 0.f, pm8 = 0.f;
#pragma unroll
        for (int nt = 0; nt < 16; nt++) {
            float2 bpv = *(float2*)(bp_s + nt * 8 + li * 2);
            float2 wov = *(float2*)(Wo_s + nt * 8 + li * 2);
            pm  += tanhf(D2[nt][0] + bpv.x) * wov.x
                 + tanhf(D2[nt][1] + bpv.y) * wov.y;
            pm8 += tanhf(D2[nt][2] + bpv.x) * wov.x
                 + tanhf(D2[nt][3] + bpv.y) * wov.y;
        }
        float vm  = omix * s1m  + mix * pm;
        float vm8 = omix * s1m8 + mix * pm8;
        vm  += __shfl_xor_sync(0xffffffffu, vm, 1);
        vm  += __shfl_xor_sync(0xffffffffu, vm, 2);
        vm8 += __shfl_xor_sync(0xffffffffu, vm8, 1);
        vm8 += __shfl_xor_sync(0xffffffffu, vm8, 2);
        if (li == 0) {
            int mr = warp * 16 + lg;
            if (base + mr < n)
                atomicAdd(&out[tk[mr]], wt[mr] * (vm + boe));
            if (base + mr + 8 < n)
                atomicAdd(&out[tk[mr + 8]], wt[mr + 8] * (vm8 + boe));
        }
    }
}

extern "C" void kernel_launch(void* const* d_in, const int* in_sizes, int n_in,
                              void* d_out, int out_size) {
    const float* feat      = (const float*)d_in[0];
    const float* Wg        = (const float*)d_in[1];
    const float* W1        = (const float*)d_in[2];
    const float* b1        = (const float*)d_in[3];
    const float* Wp        = (const float*)d_in[4];
    const float* bp        = (const float*)d_in[5];
    const float* mix_logit = (const float*)d_in[6];
    const float* Wo        = (const float*)d_in[7];
    const float* bo        = (const float*)d_in[8];
    float* out = (float*)d_out;

    cudaFuncSetAttribute(k_expert, cudaFuncAttributeMaxDynamicSharedMemorySize,
                         SMEM_BYTES);
    k_prep<<<Ev * 16, 256>>>(W1, Wp);
    k_gate<<<Bv / 8, 256>>>(feat, Wg, out);
    k_expert<<<NBv * Ev, 256, SMEM_BYTES>>>(feat, b1, bp, mix_logit, Wo, bo, out);
}

// round 9
// speedup vs baseline: 2.3468x; 1.0582x over previous
#include <cuda_runtime.h>
#include <cuda_bf16.h>
#include <math.h>
#include <stdint.h>

#define Bv 16384
#define Dv 256
#define Ev 8
#define NBv 17          // 136 blocks, one wave
#define MT 128          // tokens per tile
#define TPB 512

__device__ int   g_count[Ev];
__device__ int   g_tok[Ev][Bv];
__device__ float g_w[Ev][Bv];
// pre-swizzled bf16 weight images: W1 [e][half][hi/lo] 32KB each (1MB),
// then Wp [e][hi/lo] 32KB each (0.5MB)
__device__ uint4 g_img4[1572864 / 16];

__device__ __forceinline__ uint32_t smem_u32(const void* p) {
    uint32_t a;
    asm("{ .reg .u64 t; cvta.to.shared.u64 t, %1; cvt.u32.u64 %0, t; }"
        : "=r"(a) : "l"(p));
    return a;
}
__device__ __forceinline__ uint32_t packbf(float even, float odd) {
    uint32_t r;
    asm("cvt.rn.bf16x2.f32 %0, %1, %2;" : "=r"(r) : "f"(odd), "f"(even));
    return r;
}
__device__ __forceinline__ float blo(float v) {
    return v - __bfloat162float(__float2bfloat16(v));
}
__device__ __forceinline__ void ldsm4(uint32_t addr, uint32_t* r) {
    asm volatile("ldmatrix.sync.aligned.m8n8.x4.shared.b16 {%0,%1,%2,%3}, [%4];"
        : "=r"(r[0]), "=r"(r[1]), "=r"(r[2]), "=r"(r[3]) : "r"(addr));
}
__device__ __forceinline__ void mma_bf(float* d, const uint32_t* a,
                                       uint32_t b0, uint32_t b1) {
    asm volatile("mma.sync.aligned.m16n8k16.row.col.f32.bf16.bf16.f32 "
        "{%0,%1,%2,%3}, {%4,%5,%6,%7}, {%8,%9}, {%0,%1,%2,%3};"
        : "+f"(d[0]), "+f"(d[1]), "+f"(d[2]), "+f"(d[3])
        : "r"(a[0]), "r"(a[1]), "r"(a[2]), "r"(a[3]), "r"(b0), "r"(b1));
}

// ---- k_prep: parallel weight-image build (coalesced 4B stores) + zero ----
__global__ void __launch_bounds__(256) k_prep(const float* __restrict__ W1,
                                              const float* __restrict__ Wp) {
    const int e = blockIdx.x >> 4;
    const int p = blockIdx.x & 15;
    unsigned char* img = (unsigned char*)g_img4;
    if (blockIdx.x == 0 && threadIdx.x < Ev) g_count[threadIdx.x] = 0;

    for (int q = 0; q < 4; q++) {
        int i = (p * 4 + q) * 256 + threadIdx.x;
        int h = i >> 7, d2 = i & 127;
        int dg = d2 * 2;
        float v0 = W1[e * 32768 + dg * 128 + h];
        float v1 = W1[e * 32768 + (dg + 1) * 128 + h];
        int half = dg >> 7, dl = dg & 127;
        uint32_t off = (uint32_t)h * 256 + (((uint32_t)dl * 2) ^ ((h & 7) * 16));
        uint32_t hb = (uint32_t)((e * 2 + half) * 2) * 32768u;
        *(uint32_t*)(img + hb + off)          = packbf(v0, v1);
        *(uint32_t*)(img + hb + 32768u + off) = packbf(blo(v0), blo(v1));
    }
    for (int q = 0; q < 2; q++) {
        int i = (p * 2 + q) * 256 + threadIdx.x;
        int k = i >> 6, h2 = i & 63;
        int hg = h2 * 2;
        float v0 = Wp[e * 16384 + hg * 128 + k];
        float v1 = Wp[e * 16384 + (hg + 1) * 128 + k];
        uint32_t off = (uint32_t)k * 256 + (((uint32_t)hg * 2) ^ ((k & 7) * 16));
        uint32_t base = 1048576u + (uint32_t)(e * 2) * 32768u;
        *(uint32_t*)(img + base + off)          = packbf(v0, v1);
        *(uint32_t*)(img + base + 32768u + off) = packbf(blo(v0), blo(v1));
    }
}

__global__ void __launch_bounds__(256) k_gate(const float* __restrict__ feat,
                                              const float* __restrict__ Wg,
                                              float* __restrict__ out) {
    __shared__ float WgT[Ev * 256];
    for (int i = threadIdx.x; i < Dv * Ev; i += 256)
        WgT[(i & 7) * 256 + (i >> 3)] = Wg[i];
    __syncthreads();
    int l = threadIdx.x & 31;
    int tok = blockIdx.x * 8 + (threadIdx.x >> 5);
    if (l == 0) out[tok] = 0.f;
    const float* x = feat + (size_t)tok * Dv;
    float acc[Ev];
#pragma unroll
    for (int e = 0; e < Ev; e++) acc[e] = 0.f;
#pragma unroll
    for (int d0 = 0; d0 < Dv; d0 += 128) {
        float4 x4 = *(const float4*)(x + d0 + l * 4);
#pragma unroll
        for (int e = 0; e < Ev; e++) {
            const float* wr = WgT + e * 256 + d0 + l * 4;
            acc[e] += x4.x * wr[0] + x4.y * wr[1] + x4.z * wr[2] + x4.w * wr[3];
        }
    }
#pragma unroll
    for (int e = 0; e < Ev; e++)
#pragma unroll
        for (int off = 16; off; off >>= 1)
            acc[e] += __shfl_down_sync(0xffffffffu, acc[e], off);
    if (l == 0) {
        float m = acc[0];
#pragma unroll
        for (int e = 1; e < Ev; e++) m = fmaxf(m, acc[e]);
        float g[Ev], sum = 0.f;
#pragma unroll
        for (int e = 0; e < Ev; e++) { g[e] = expf(acc[e] - m); sum += g[e]; }
        float inv = 1.f / sum;
#pragma unroll
        for (int e = 0; e < Ev; e++) g[e] *= inv;
        int i0 = 0;
#pragma unroll
        for (int e = 1; e < Ev; e++) if (g[e] > g[i0]) i0 = e;
        int i1 = -1;
#pragma unroll
        for (int e = 0; e < Ev; e++) {
            if (e == i0) continue;
            if (i1 < 0 || g[e] > g[i1]) i1 = e;
        }
        float denom = g[i0] + g[i1] + 1e-10f;
        int r0 = atomicAdd(&g_count[i0], 1);
        g_tok[i0][r0] = tok; g_w[i0][r0] = g[i0] / denom;
        int r1 = atomicAdd(&g_count[i1], 1);
        g_tok[i1][r1] = tok; g_w[i1][r1] = g[i1] / denom;
    }
}

// smem: Ahi 0 (32K) [core_hi after GEMM1], Alo 32768 [core_lo],
//       W1h_hi 65536, W1h_lo 98304, Wp_hi 131072, Wp_lo 163840,
//       tk 196608, wt 197120, b1 197632, bp 198144, Wo 198656 -> 199168
#define OFF_AHI 0
#define OFF_ALO 32768
#define OFF_WH  65536
#define OFF_WL  98304
#define OFF_PH  131072
#define OFF_PL  163840
#define SMEM_BYTES 199168

__global__ void __launch_bounds__(TPB, 1) k_expert(
    const float* __restrict__ feat,
    const float* __restrict__ b1g, const float* __restrict__ bpg,
    const float* __restrict__ mix_logit,
    const float* __restrict__ Wog, const float* __restrict__ bog,
    float* __restrict__ out)
{
    extern __shared__ __align__(1024) char smb[];
    int*   tk   = (int*)(smb + 196608);
    float* wt   = (float*)(smb + 197120);
    float* b1_s = (float*)(smb + 197632);
    float* bp_s = (float*)(smb + 198144);
    float* Wo_s = (float*)(smb + 198656);

    const int e    = blockIdx.x & 7;
    const int j    = blockIdx.x >> 3;
    const int tid  = threadIdx.x;
    const int warp = tid >> 5;
    const int lane = tid & 31;
    const int mw   = warp & 7;     // M group (16 tokens)
    const int nh   = warp >> 3;    // N half (64 h's)
    const int li   = lane & 3;
    const int lg   = lane >> 2;
    const uint32_t sb = smem_u32(smb);

    // stage Wp images (resident) + biases
    {
        const uint4* s = g_img4 + 65536 + (size_t)(e * 2) * 2048;
        uint4* dH = (uint4*)(smb + OFF_PH);
        uint4* dL = (uint4*)(smb + OFF_PL);
        for (int u = tid; u < 2048; u += TPB) { dH[u] = s[u]; dL[u] = s[u + 2048]; }
    }
    if (tid < 128) {
        b1_s[tid] = b1g[e * 128 + tid];
        bp_s[tid] = bpg[e * 128 + tid];
        Wo_s[tid] = Wog[e * 128 + tid];
    }
    const float mix  = 1.f / (1.f + expf(-mix_logit[e]));
    const float omix = 1.f - mix;
    const float boe  = (nh == 0) ? bog[e] : 0.f;  // add bias once per token
    const int   n    = g_count[e];

    // fragment addressing (swizzle: byte = row*256 + (kbyte ^ ((row&7)*16)))
    const int matA = lane >> 3;
    const int arow = mw * 16 + (matA & 1) * 8 + (lane & 7);
    const uint32_t a_koff = (uint32_t)(matA >> 1) * 16;
    const uint32_t a_sw   = (uint32_t)(arow & 7) * 16;
    const uint32_t a_rowb = (uint32_t)arow * 256;
    const int jt = matA >> 1, kc = matA & 1;
    const int brow_lo = nh * 64 + jt * 8 + (lane & 7);   // + ntp*16
    const uint32_t b_koff = (uint32_t)kc * 16;

    for (int tile = j; tile * MT < n; tile += NBv) {
        const int base = tile * MT;
        __syncthreads();                 // prev GEMM2 core-reads done
        if (tid < 128) {
            int idx = min(base + tid, n - 1);
            tk[tid] = g_tok[e][idx];
            wt[tid] = g_w[e][idx];
        }

        float D1[8][4];
#pragma unroll
        for (int t = 0; t < 8; t++)
#pragma unroll
            for (int q = 0; q < 4; q++) D1[t][q] = 0.f;

        // ===== GEMM1: D1 = x @ W1 (this warp's 64-h slice), 3-pass bf16 =====
        for (int half = 0; half < 2; half++) {
            __syncthreads();             // safe to overwrite A/W staging
            for (int u = tid; u < 4096; u += TPB) {
                int ts = u >> 5, d = (u & 31) * 4;
                float4 x4 = *(const float4*)(feat + (size_t)tk[ts] * Dv
                                             + half * 128 + d);
                uint32_t off = (uint32_t)ts * 256
                             + (((uint32_t)d * 2) ^ ((ts & 7) * 16));
                *(uint2*)(smb + OFF_AHI + off) =
                    make_uint2(packbf(x4.x, x4.y), packbf(x4.z, x4.w));
                *(uint2*)(smb + OFF_ALO + off) =
                    make_uint2(packbf(blo(x4.x), blo(x4.y)),
                               packbf(blo(x4.z), blo(x4.w)));
            }
            {
                const uint4* s = g_img4 + (size_t)((e * 2 + half) * 2) * 2048;
                uint4* dH = (uint4*)(smb + OFF_WH);
                uint4* dL = (uint4*)(smb + OFF_WL);
                for (int u = tid; u < 2048; u += TPB) {
                    dH[u] = s[u]; dL[u] = s[u + 2048];
                }
            }
            __syncthreads();

            for (int ks = 0; ks < 8; ks++) {
                uint32_t akx = (((uint32_t)ks * 32 + a_koff) ^ a_sw) + a_rowb;
                uint32_t ah[4], al[4];
                ldsm4(sb + OFF_AHI + akx, ah);
                ldsm4(sb + OFF_ALO + akx, al);
#pragma unroll
                for (int ntp = 0; ntp < 4; ntp++) {
                    int brow = ntp * 16 + brow_lo;
                    uint32_t bkx = (((uint32_t)ks * 32 + b_koff)
                                    ^ ((brow & 7) * 16)) + (uint32_t)brow * 256;
                    uint32_t bh[4], bl[4];
                    ldsm4(sb + OFF_WH + bkx, bh);
                    ldsm4(sb + OFF_WL + bkx, bl);
                    mma_bf(D1[2 * ntp],     ah, bh[0], bh[1]);
                    mma_bf(D1[2 * ntp + 1], ah, bh[2], bh[3]);
                    mma_bf(D1[2 * ntp],     ah, bl[0], bl[1]);
                    mma_bf(D1[2 * ntp + 1], ah, bl[2], bl[3]);
                    mma_bf(D1[2 * ntp],     al, bh[0], bh[1]);
                    mma_bf(D1[2 * ntp + 1], al, bh[2], bh[3]);
                }
            }
        }

        // ===== epilogue 1: relu+b1; partial Wo-dot; core -> smem bf16 hi/lo =====
        __syncthreads();                 // all GEMM1 A-reads done -> reuse as core
        float s1m = 0.f, s1m8 = 0.f;
        {
            const int tok0 = mw * 16 + lg;
            const uint32_t sw0 = (uint32_t)(tok0 & 7) * 16;
            const uint32_t sw1 = (uint32_t)((tok0 + 8) & 7) * 16;
#pragma unroll
            for (int t = 0; t < 8; t++) {
                int h0 = nh * 64 + (t >> 1) * 16 + (t & 1) * 8 + li * 2;
                float2 b1v = *(float2*)(b1_s + h0);
                float2 wov = *(float2*)(Wo_s + h0);
                float c0 = fmaxf(D1[t][0] + b1v.x, 0.f);
                float c1 = fmaxf(D1[t][1] + b1v.y, 0.f);
                float c2 = fmaxf(D1[t][2] + b1v.x, 0.f);
                float c3 = fmaxf(D1[t][3] + b1v.y, 0.f);
                s1m  += c0 * wov.x + c1 * wov.y;
                s1m8 += c2 * wov.x + c3 * wov.y;
                uint32_t col = (uint32_t)h0 * 2;
                uint32_t o0 = (uint32_t)tok0 * 256 + (col ^ sw0);
                uint32_t o1 = (uint32_t)(tok0 + 8) * 256 + (col ^ sw1);
                *(uint32_t*)(smb + OFF_AHI + o0) = packbf(c0, c1);
                *(uint32_t*)(smb + OFF_ALO + o0) = packbf(blo(c0), blo(c1));
                *(uint32_t*)(smb + OFF_AHI + o1) = packbf(c2, c3);
                *(uint32_t*)(smb + OFF_ALO + o1) = packbf(blo(c2), blo(c3));
            }
        }
        __syncthreads();

        // ===== GEMM2: D2 = core @ Wp (A from core smem, B resident) =====
        float D2[8][4];
#pragma unroll
        for (int t = 0; t < 8; t++)
#pragma unroll
            for (int q = 0; q < 4; q++) D2[t][q] = 0.f;
        for (int ks = 0; ks < 8; ks++) {
            uint32_t akx = (((uint32_t)ks * 32 + a_koff) ^ a_sw) + a_rowb;
            uint32_t ah[4], al[4];
            ldsm4(sb + OFF_AHI + akx, ah);
            ldsm4(sb + OFF_ALO + akx, al);
#pragma unroll
            for (int ntp = 0; ntp < 4; ntp++) {
                int brow = ntp * 16 + brow_lo;
                uint32_t bkx = (((uint32_t)ks * 32 + b_koff)
                                ^ ((brow & 7) * 16)) + (uint32_t)brow * 256;
                uint32_t bh[4], bl[4];
                ldsm4(sb + OFF_PH + bkx, bh);
                ldsm4(sb + OFF_PL + bkx, bl);
                mma_bf(D2[2 * ntp],     ah, bh[0], bh[1]);
                mma_bf(D2[2 * ntp + 1], ah, bh[2], bh[3]);
                mma_bf(D2[2 * ntp],     ah, bl[0], bl[1]);
                mma_bf(D2[2 * ntp + 1], ah, bl[2], bl[3]);
                mma_bf(D2[2 * ntp],     al, bh[0], bh[1]);
                mma_bf(D2[2 * ntp + 1], al, bh[2], bh[3]);
            }
        }

        // ===== epilogue 2: tanh + mix + Wo dot + quad-reduce + atomicAdd =====
        float pm = 0.f, pm8 = 0.f;
#pragma unroll
        for (int t = 0; t < 8; t++) {
            int h0 = nh * 64 + (t >> 1) * 16 + (t & 1) * 8 + li * 2;
            float2 bpv = *(float2*)(bp_s + h0);
            float2 wov = *(float2*)(Wo_s + h0);
            pm  += tanhf(D2[t][0] + bpv.x) * wov.x
                 + tanhf(D2[t][1] + bpv.y) * wov.y;
            pm8 += tanhf(D2[t][2] + bpv.x) * wov.x
                 + tanhf(D2[t][3] + bpv.y) * wov.y;
        }
        float vm  = omix * s1m  + mix * pm  + boe;
        float vm8 = omix * s1m8 + mix * pm8 + boe;
        vm  += __shfl_xor_sync(0xffffffffu, vm, 1);
        vm  += __shfl_xor_sync(0xffffffffu, vm, 2);
        vm8 += __shfl_xor_sync(0xffffffffu, vm8, 1);
        vm8 += __shfl_xor_sync(0xffffffffu, vm8, 2);
        if (li == 0) {
            int mr = mw * 16 + lg;
            // boe folded per-lane: ×4 lanes summed -> subtract 3x
            float corr = 3.f * boe;
            if (base + mr < n)
                atomicAdd(&out[tk[mr]], wt[mr] * (vm - corr));
            if (base + mr + 8 < n)
                atomicAdd(&out[tk[mr + 8]], wt[mr + 8] * (vm8 - corr));
        }
    }
}

extern "C" void kernel_launch(void* const* d_in, const int* in_sizes, int n_in,
                              void* d_out, int out_size) {
    const float* feat      = (const float*)d_in[0];
    const float* Wg        = (const float*)d_in[1];
    const float* W1        = (const float*)d_in[2];
    const float* b1        = (const float*)d_in[3];
    const float* Wp        = (const float*)d_in[4];
    const float* bp        = (const float*)d_in[5];
    const float* mix_logit = (const float*)d_in[6];
    const float* Wo        = (const float*)d_in[7];
    const float* bo        = (const float*)d_in[8];
    float* out = (float*)d_out;

    cudaFuncSetAttribute(k_expert, cudaFuncAttributeMaxDynamicSharedMemorySize,
                         SMEM_BYTES);
    k_prep<<<Ev * 16, 256>>>(W1, Wp);
    k_gate<<<Bv / 8, 256>>>(feat, Wg, out);
    k_expert<<<NBv * Ev, TPB, SMEM_BYTES>>>(feat, b1, bp, mix_logit, Wo, bo, out);
}

// round 10
// speedup vs baseline: 2.3498x; 1.0013x over previous
#include <cuda_runtime.h>
#include <cuda_bf16.h>
#include <math.h>
#include <stdint.h>

#define Bv 16384
#define Dv 256
#define Ev 8
#define NBv 17          // 136 blocks, one wave
#define MT 128          // tokens per tile
#define TPB 512

__device__ int   g_count[Ev];
__device__ int   g_tok[Ev][Bv];
__device__ float g_w[Ev][Bv];
// pre-swizzled bf16 weight images: W1 [e][half][hi/lo] 32KB each (1MB),
// then Wp [e][hi/lo] 32KB each (0.5MB)
__device__ uint4 g_img4[1572864 / 16];

__device__ __forceinline__ uint32_t smem_u32(const void* p) {
    uint32_t a;
    asm("{ .reg .u64 t; cvta.to.shared.u64 t, %1; cvt.u32.u64 %0, t; }"
        : "=r"(a) : "l"(p));
    return a;
}
__device__ __forceinline__ uint32_t packbf(float even, float odd) {
    uint32_t r;
    asm("cvt.rn.bf16x2.f32 %0, %1, %2;" : "=r"(r) : "f"(odd), "f"(even));
    return r;
}
__device__ __forceinline__ float blo(float v) {
    return v - __bfloat162float(__float2bfloat16(v));
}
__device__ __forceinline__ void ldsm4(uint32_t addr, uint32_t* r) {
    asm volatile("ldmatrix.sync.aligned.m8n8.x4.shared.b16 {%0,%1,%2,%3}, [%4];"
        : "=r"(r[0]), "=r"(r[1]), "=r"(r[2]), "=r"(r[3]) : "r"(addr));
}
__device__ __forceinline__ void mma_bf(float* d, const uint32_t* a,
                                       uint32_t b0, uint32_t b1) {
    asm volatile("mma.sync.aligned.m16n8k16.row.col.f32.bf16.bf16.f32 "
        "{%0,%1,%2,%3}, {%4,%5,%6,%7}, {%8,%9}, {%0,%1,%2,%3};"
        : "+f"(d[0]), "+f"(d[1]), "+f"(d[2]), "+f"(d[3])
        : "r"(a[0]), "r"(a[1]), "r"(a[2]), "r"(a[3]), "r"(b0), "r"(b1));
}

// ---- k_prep: parallel weight-image build (coalesced 4B stores) + zero ----
__global__ void __launch_bounds__(256) k_prep(const float* __restrict__ W1,
                                              const float* __restrict__ Wp) {
    const int e = blockIdx.x >> 4;
    const int p = blockIdx.x & 15;
    unsigned char* img = (unsigned char*)g_img4;
    if (blockIdx.x == 0 && threadIdx.x < Ev) g_count[threadIdx.x] = 0;

    for (int q = 0; q < 4; q++) {
        int i = (p * 4 + q) * 256 + threadIdx.x;
        int h = i >> 7, d2 = i & 127;
        int dg = d2 * 2;
        float v0 = W1[e * 32768 + dg * 128 + h];
        float v1 = W1[e * 32768 + (dg + 1) * 128 + h];
        int half = dg >> 7, dl = dg & 127;
        uint32_t off = (uint32_t)h * 256 + (((uint32_t)dl * 2) ^ ((h & 7) * 16));
        uint32_t hb = (uint32_t)((e * 2 + half) * 2) * 32768u;
        *(uint32_t*)(img + hb + off)          = packbf(v0, v1);
        *(uint32_t*)(img + hb + 32768u + off) = packbf(blo(v0), blo(v1));
    }
    for (int q = 0; q < 2; q++) {
        int i = (p * 2 + q) * 256 + threadIdx.x;
        int k = i >> 6, h2 = i & 63;
        int hg = h2 * 2;
        float v0 = Wp[e * 16384 + hg * 128 + k];
        float v1 = Wp[e * 16384 + (hg + 1) * 128 + k];
        uint32_t off = (uint32_t)k * 256 + (((uint32_t)hg * 2) ^ ((k & 7) * 16));
        uint32_t base = 1048576u + (uint32_t)(e * 2) * 32768u;
        *(uint32_t*)(img + base + off)          = packbf(v0, v1);
        *(uint32_t*)(img + base + 32768u + off) = packbf(blo(v0), blo(v1));
    }
}

__global__ void __launch_bounds__(256) k_gate(const float* __restrict__ feat,
                                              const float* __restrict__ Wg,
                                              float* __restrict__ out) {
    __shared__ float WgT[Ev * 256];
    for (int i = threadIdx.x; i < Dv * Ev; i += 256)
        WgT[(i & 7) * 256 + (i >> 3)] = Wg[i];
    __syncthreads();
    int l = threadIdx.x & 31;
    int tok = blockIdx.x * 8 + (threadIdx.x >> 5);
    if (l == 0) out[tok] = 0.f;
    const float* x = feat + (size_t)tok * Dv;
    float acc[Ev];
#pragma unroll
    for (int e = 0; e < Ev; e++) acc[e] = 0.f;
#pragma unroll
    for (int d0 = 0; d0 < Dv; d0 += 128) {
        float4 x4 = *(const float4*)(x + d0 + l * 4);
#pragma unroll
        for (int e = 0; e < Ev; e++) {
            const float* wr = WgT + e * 256 + d0 + l * 4;
            acc[e] += x4.x * wr[0] + x4.y * wr[1] + x4.z * wr[2] + x4.w * wr[3];
        }
    }
#pragma unroll
    for (int e = 0; e < Ev; e++)
#pragma unroll
        for (int off = 16; off; off >>= 1)
            acc[e] += __shfl_down_sync(0xffffffffu, acc[e], off);
    if (l == 0) {
        float m = acc[0];
#pragma unroll
        for (int e = 1; e < Ev; e++) m = fmaxf(m, acc[e]);
        float g[Ev], sum = 0.f;
#pragma unroll
        for (int e = 0; e < Ev; e++) { g[e] = expf(acc[e] - m); sum += g[e]; }
        float inv = 1.f / sum;
#pragma unroll
        for (int e = 0; e < Ev; e++) g[e] *= inv;
        int i0 = 0;
#pragma unroll
        for (int e = 1; e < Ev; e++) if (g[e] > g[i0]) i0 = e;
        int i1 = -1;
#pragma unroll
        for (int e = 0; e < Ev; e++) {
            if (e == i0) continue;
            if (i1 < 0 || g[e] > g[i1]) i1 = e;
        }
        float denom = g[i0] + g[i1] + 1e-10f;
        int r0 = atomicAdd(&g_count[i0], 1);
        g_tok[i0][r0] = tok; g_w[i0][r0] = g[i0] / denom;
        int r1 = atomicAdd(&g_count[i1], 1);
        g_tok[i1][r1] = tok; g_w[i1][r1] = g[i1] / denom;
    }
}

// smem: Ahi 0 (32K) [core_hi after GEMM1], Alo 32768 [core_lo],
//       W1h_hi 65536, W1h_lo 98304, Wp_hi 131072, Wp_lo 163840,
//       tk 196608, wt 197120, b1 197632, bp 198144, Wo 198656 -> 199168
#define OFF_AHI 0
#define OFF_ALO 32768
#define OFF_WH  65536
#define OFF_WL  98304
#define OFF_PH  131072
#define OFF_PL  163840
#define SMEM_BYTES 199168

__global__ void __launch_bounds__(TPB, 1) k_expert(
    const float* __restrict__ feat,
    const float* __restrict__ b1g, const float* __restrict__ bpg,
    const float* __restrict__ mix_logit,
    const float* __restrict__ Wog, const float* __restrict__ bog,
    float* __restrict__ out)
{
    extern __shared__ __align__(1024) char smb[];
    int*   tk   = (int*)(smb + 196608);
    float* wt   = (float*)(smb + 197120);
    float* b1_s = (float*)(smb + 197632);
    float* bp_s = (float*)(smb + 198144);
    float* Wo_s = (float*)(smb + 198656);

    const int e    = blockIdx.x & 7;
    const int j    = blockIdx.x >> 3;
    const int tid  = threadIdx.x;
    const int warp = tid >> 5;
    const int lane = tid & 31;
    const int mw   = warp & 3;     // M group: 32 tokens (two 16-row strips)
    const int nh   = warp >> 2;    // N quarter: 32 h's
    const int li   = lane & 3;
    const int lg   = lane >> 2;
    const uint32_t sb = smem_u32(smb);

    // stage Wp images (resident) + biases
    {
        const uint4* s = g_img4 + 65536 + (size_t)(e * 2) * 2048;
        uint4* dH = (uint4*)(smb + OFF_PH);
        uint4* dL = (uint4*)(smb + OFF_PL);
        for (int u = tid; u < 2048; u += TPB) { dH[u] = s[u]; dL[u] = s[u + 2048]; }
    }
    if (tid < 128) {
        b1_s[tid] = b1g[e * 128 + tid];
        bp_s[tid] = bpg[e * 128 + tid];
        Wo_s[tid] = Wog[e * 128 + tid];
    }
    const float mix  = 1.f / (1.f + expf(-mix_logit[e]));
    const float omix = 1.f - mix;
    const float boe  = (nh == 0) ? bog[e] : 0.f;   // add once per token
    const int   n    = g_count[e];

    // fragment addressing (swizzle: byte = row*256 + (kbyte ^ ((row&7)*16)))
    const int matA = lane >> 3;
    const uint32_t a_koff = (uint32_t)(matA >> 1) * 16;
    const uint32_t sw     = (uint32_t)(lane & 7) * 16;  // row&7 == lane&7 always
    const uint32_t arow0  = (uint32_t)(mw * 32 + (matA & 1) * 8 + (lane & 7));
    const int jt = matA >> 1, kc = matA & 1;
    const uint32_t brow0  = (uint32_t)(nh * 32 + jt * 8 + (lane & 7)); // +ntp*16
    const uint32_t b_koff = (uint32_t)kc * 16;

    for (int tile = j; tile * MT < n; tile += NBv) {
        const int base = tile * MT;
        __syncthreads();                 // prev GEMM2 core-reads done
        if (tid < 128) {
            int idx = min(base + tid, n - 1);
            tk[tid] = g_tok[e][idx];
            wt[tid] = g_w[e][idx];
        }

        float D1[2][4][4];               // [strip][ntp*2+p8][regs]
#pragma unroll
        for (int s = 0; s < 2; s++)
#pragma unroll
            for (int t = 0; t < 4; t++)
#pragma unroll
                for (int q = 0; q < 4; q++) D1[s][t][q] = 0.f;

        // ===== GEMM1: D1 = x @ W1 (32 tok x 32 h slice), 3-pass bf16 =====
        for (int half = 0; half < 2; half++) {
            __syncthreads();             // safe to overwrite A/W staging
            for (int u = tid; u < 4096; u += TPB) {
                int ts = u >> 5, d = (u & 31) * 4;
                float4 x4 = *(const float4*)(feat + (size_t)tk[ts] * Dv
                                             + half * 128 + d);
                uint32_t off = (uint32_t)ts * 256
                             + (((uint32_t)d * 2) ^ ((ts & 7) * 16));
                *(uint2*)(smb + OFF_AHI + off) =
                    make_uint2(packbf(x4.x, x4.y), packbf(x4.z, x4.w));
                *(uint2*)(smb + OFF_ALO + off) =
                    make_uint2(packbf(blo(x4.x), blo(x4.y)),
                               packbf(blo(x4.z), blo(x4.w)));
            }
            {
                const uint4* s = g_img4 + (size_t)((e * 2 + half) * 2) * 2048;
                uint4* dH = (uint4*)(smb + OFF_WH);
                uint4* dL = (uint4*)(smb + OFF_WL);
                for (int u = tid; u < 2048; u += TPB) {
                    dH[u] = s[u]; dL[u] = s[u + 2048];
                }
            }
            __syncthreads();

            for (int ks = 0; ks < 8; ks++) {
                uint32_t kx  = (uint32_t)ks * 32;
                uint32_t akx = (kx + a_koff) ^ sw;
                uint32_t ah0[4], al0[4], ah1[4], al1[4];
                ldsm4(sb + OFF_AHI + arow0 * 256 + akx, ah0);
                ldsm4(sb + OFF_ALO + arow0 * 256 + akx, al0);
                ldsm4(sb + OFF_AHI + (arow0 + 16) * 256 + akx, ah1);
                ldsm4(sb + OFF_ALO + (arow0 + 16) * 256 + akx, al1);
#pragma unroll
                for (int ntp = 0; ntp < 2; ntp++) {
                    uint32_t bkx = ((kx + b_koff) ^ sw)
                                 + (brow0 + ntp * 16) * 256;
                    uint32_t bh[4], bl[4];
                    ldsm4(sb + OFF_WH + bkx, bh);
                    ldsm4(sb + OFF_WL + bkx, bl);
                    mma_bf(D1[0][2 * ntp],     ah0, bh[0], bh[1]);
                    mma_bf(D1[0][2 * ntp + 1], ah0, bh[2], bh[3]);
                    mma_bf(D1[1][2 * ntp],     ah1, bh[0], bh[1]);
                    mma_bf(D1[1][2 * ntp + 1], ah1, bh[2], bh[3]);
                    mma_bf(D1[0][2 * ntp],     ah0, bl[0], bl[1]);
                    mma_bf(D1[0][2 * ntp + 1], ah0, bl[2], bl[3]);
                    mma_bf(D1[1][2 * ntp],     ah1, bl[0], bl[1]);
                    mma_bf(D1[1][2 * ntp + 1], ah1, bl[2], bl[3]);
                    mma_bf(D1[0][2 * ntp],     al0, bh[0], bh[1]);
                    mma_bf(D1[0][2 * ntp + 1], al0, bh[2], bh[3]);
                    mma_bf(D1[1][2 * ntp],     al1, bh[0], bh[1]);
                    mma_bf(D1[1][2 * ntp + 1], al1, bh[2], bh[3]);
                }
            }
        }

        // ===== epilogue 1: relu+b1; partial Wo-dot; core -> smem bf16 hi/lo =====
        __syncthreads();                 // GEMM1 A-reads done -> reuse as core
        float s1[2][2];                  // [strip][row lg / lg+8]
        {
#pragma unroll
            for (int s = 0; s < 2; s++) {
                const int tok0 = mw * 32 + s * 16 + lg;
                const uint32_t sw0 = (uint32_t)(tok0 & 7) * 16;
                const uint32_t sw1 = (uint32_t)((tok0 + 8) & 7) * 16;
                float a = 0.f, b = 0.f;
#pragma unroll
                for (int t = 0; t < 4; t++) {
                    int h0 = nh * 32 + (t >> 1) * 16 + (t & 1) * 8 + li * 2;
                    float2 b1v = *(float2*)(b1_s + h0);
                    float2 wov = *(float2*)(Wo_s + h0);
                    float c0 = fmaxf(D1[s][t][0] + b1v.x, 0.f);
                    float c1 = fmaxf(D1[s][t][1] + b1v.y, 0.f);
                    float c2 = fmaxf(D1[s][t][2] + b1v.x, 0.f);
                    float c3 = fmaxf(D1[s][t][3] + b1v.y, 0.f);
                    a += c0 * wov.x + c1 * wov.y;
                    b += c2 * wov.x + c3 * wov.y;
                    uint32_t col = (uint32_t)h0 * 2;
                    uint32_t o0 = (uint32_t)tok0 * 256 + (col ^ sw0);
                    uint32_t o1 = (uint32_t)(tok0 + 8) * 256 + (col ^ sw1);
                    *(uint32_t*)(smb + OFF_AHI + o0) = packbf(c0, c1);
                    *(uint32_t*)(smb + OFF_ALO + o0) = packbf(blo(c0), blo(c1));
                    *(uint32_t*)(smb + OFF_AHI + o1) = packbf(c2, c3);
                    *(uint32_t*)(smb + OFF_ALO + o1) = packbf(blo(c2), blo(c3));
                }
                s1[s][0] = a; s1[s][1] = b;
            }
        }
        __syncthreads();

        // ===== GEMM2: D2 = core @ Wp (A from core smem, B resident) =====
        float D2[2][4][4];
#pragma unroll
        for (int s = 0; s < 2; s++)
#pragma unroll
            for (int t = 0; t < 4; t++)
#pragma unroll
                for (int q = 0; q < 4; q++) D2[s][t][q] = 0.f;
        for (int ks = 0; ks < 8; ks++) {
            uint32_t kx  = (uint32_t)ks * 32;
            uint32_t akx = (kx + a_koff) ^ sw;
            uint32_t ah0[4], al0[4], ah1[4], al1[4];
            ldsm4(sb + OFF_AHI + arow0 * 256 + akx, ah0);
            ldsm4(sb + OFF_ALO + arow0 * 256 + akx, al0);
            ldsm4(sb + OFF_AHI + (arow0 + 16) * 256 + akx, ah1);
            ldsm4(sb + OFF_ALO + (arow0 + 16) * 256 + akx, al1);
#pragma unroll
            for (int ntp = 0; ntp < 2; ntp++) {
                uint32_t bkx = ((kx + b_koff) ^ sw) + (brow0 + ntp * 16) * 256;
                uint32_t bh[4], bl[4];
                ldsm4(sb + OFF_PH + bkx, bh);
                ldsm4(sb + OFF_PL + bkx, bl);
                mma_bf(D2[0][2 * ntp],     ah0, bh[0], bh[1]);
                mma_bf(D2[0][2 * ntp + 1], ah0, bh[2], bh[3]);
                mma_bf(D2[1][2 * ntp],     ah1, bh[0], bh[1]);
                mma_bf(D2[1][2 * ntp + 1], ah1, bh[2], bh[3]);
                mma_bf(D2[0][2 * ntp],     ah0, bl[0], bl[1]);
                mma_bf(D2[0][2 * ntp + 1], ah0, bl[2], bl[3]);
                mma_bf(D2[1][2 * ntp],     ah1, bl[0], bl[1]);
                mma_bf(D2[1][2 * ntp + 1], ah1, bl[2], bl[3]);
                mma_bf(D2[0][2 * ntp],     al0, bh[0], bh[1]);
                mma_bf(D2[0][2 * ntp + 1], al0, bh[2], bh[3]);
                mma_bf(D2[1][2 * ntp],     al1, bh[0], bh[1]);
                mma_bf(D2[1][2 * ntp + 1], al1, bh[2], bh[3]);
            }
        }

        // ===== epilogue 2: tanh + mix + Wo dot + quad-reduce + atomicAdd =====
#pragma unroll
        for (int s = 0; s < 2; s++) {
            float pa = 0.f, pb = 0.f;
#pragma unroll
            for (int t = 0; t < 4; t++) {
                int h0 = nh * 32 + (t >> 1) * 16 + (t & 1) * 8 + li * 2;
                float2 bpv = *(float2*)(bp_s + h0);
                float2 wov = *(float2*)(Wo_s + h0);
                pa += tanhf(D2[s][t][0] + bpv.x) * wov.x
                    + tanhf(D2[s][t][1] + bpv.y) * wov.y;
                pb += tanhf(D2[s][t][2] + bpv.x) * wov.x
                    + tanhf(D2[s][t][3] + bpv.y) * wov.y;
            }
            float va = omix * s1[s][0] + mix * pa + boe;
            float vb = omix * s1[s][1] + mix * pb + boe;
            va += __shfl_xor_sync(0xffffffffu, va, 1);
            va += __shfl_xor_sync(0xffffffffu, va, 2);
            vb += __shfl_xor_sync(0xffffffffu, vb, 1);
            vb += __shfl_xor_sync(0xffffffffu, vb, 2);
            if (li == 0) {
                int mr = mw * 32 + s * 16 + lg;
                float corr = 3.f * boe;   // boe added by all 4 quad lanes
                if (base + mr < n)
                    atomicAdd(&out[tk[mr]], wt[mr] * (va - corr));
                if (base + mr + 8 < n)
                    atomicAdd(&out[tk[mr + 8]], wt[mr + 8] * (vb - corr));
            }
        }
    }
}

extern "C" void kernel_launch(void* const* d_in, const int* in_sizes, int n_in,
                              void* d_out, int out_size) {
    const float* feat      = (const float*)d_in[0];
    const float* Wg        = (const float*)d_in[1];
    const float* W1        = (const float*)d_in[2];
    const float* b1        = (const float*)d_in[3];
    const float* Wp        = (const float*)d_in[4];
    const float* bp        = (const float*)d_in[5];
    const float* mix_logit = (const float*)d_in[6];
    const float* Wo        = (const float*)d_in[7];
    const float* bo        = (const float*)d_in[8];
    float* out = (float*)d_out;

    cudaFuncSetAttribute(k_expert, cudaFuncAttributeMaxDynamicSharedMemorySize,
                         SMEM_BYTES);
    k_prep<<<Ev * 16, 256>>>(W1, Wp);
    k_gate<<<Bv / 8, 256>>>(feat, Wg, out);
    k_expert<<<NBv * Ev, TPB, SMEM_BYTES>>>(feat, b1, bp, mix_logit, Wo, bo, out);
}

// round 11
// speedup vs baseline: 2.4129x; 1.0269x over previous
#include <cuda_runtime.h>
#include <cuda_bf16.h>
#include <math.h>
#include <stdint.h>

#define Bv 16384
#define Dv 256
#define Ev 8
#define NBv 17          // blocks per expert -> 136 blocks, one wave
#define MT 256          // tokens per tile (ONE tile per block)
#define TPB 512

__device__ int   g_count[Ev];
__device__ int   g_tok[Ev][Bv];
__device__ float g_w[Ev][Bv];
// images: W1 [e][quarter(4)][hi/lo] 16KB each (1MB), Wp [e][hi/lo] 32KB (0.5MB)
__device__ uint4 g_img4[1572864 / 16];

__device__ __forceinline__ uint32_t smem_u32(const void* p) {
    uint32_t a;
    asm("{ .reg .u64 t; cvta.to.shared.u64 t, %1; cvt.u32.u64 %0, t; }"
        : "=r"(a) : "l"(p));
    return a;
}
__device__ __forceinline__ uint32_t packbf(float even, float odd) {
    uint32_t r;
    asm("cvt.rn.bf16x2.f32 %0, %1, %2;" : "=r"(r) : "f"(odd), "f"(even));
    return r;
}
__device__ __forceinline__ float blo(float v) {
    return v - __bfloat162float(__float2bfloat16(v));
}
__device__ __forceinline__ void ldsm4(uint32_t addr, uint32_t* r) {
    asm volatile("ldmatrix.sync.aligned.m8n8.x4.shared.b16 {%0,%1,%2,%3}, [%4];"
        : "=r"(r[0]), "=r"(r[1]), "=r"(r[2]), "=r"(r[3]) : "r"(addr));
}
__device__ __forceinline__ void mma_bf(float* d, const uint32_t* a,
                                       uint32_t b0, uint32_t b1) {
    asm volatile("mma.sync.aligned.m16n8k16.row.col.f32.bf16.bf16.f32 "
        "{%0,%1,%2,%3}, {%4,%5,%6,%7}, {%8,%9}, {%0,%1,%2,%3};"
        : "+f"(d[0]), "+f"(d[1]), "+f"(d[2]), "+f"(d[3])
        : "r"(a[0]), "r"(a[1]), "r"(a[2]), "r"(a[3]), "r"(b0), "r"(b1));
}

// ---- k_prep: quarter-blocked W1 image (128B rows) + Wp image (256B rows) ----
__global__ void __launch_bounds__(256) k_prep(const float* __restrict__ W1,
                                              const float* __restrict__ Wp) {
    const int e = blockIdx.x >> 4;
    const int p = blockIdx.x & 15;
    unsigned char* img = (unsigned char*)g_img4;
    if (blockIdx.x == 0 && threadIdx.x < Ev) g_count[threadIdx.x] = 0;

    // W1[e][d][h] -> quarter q=d>>6 image: row h (128B), col dl=d&63
    for (int qq = 0; qq < 4; qq++) {
        int i = (p * 4 + qq) * 256 + threadIdx.x;     // 0..16383 pair items
        int h = i >> 7, d2 = i & 127;
        int dg = d2 * 2;
        float v0 = W1[e * 32768 + dg * 128 + h];
        float v1 = W1[e * 32768 + (dg + 1) * 128 + h];
        int quarter = dg >> 6, dl = dg & 63;
        uint32_t off = (uint32_t)h * 128 + (((uint32_t)dl * 2) ^ ((h & 7) * 16));
        uint32_t hb = (uint32_t)((e * 4 + quarter) * 2) * 16384u;
        *(uint32_t*)(img + hb + off)          = packbf(v0, v1);
        *(uint32_t*)(img + hb + 16384u + off) = packbf(blo(v0), blo(v1));
    }
    // Wp[e][h][k] -> row k (256B), col h
    for (int qq = 0; qq < 2; qq++) {
        int i = (p * 2 + qq) * 256 + threadIdx.x;     // 0..8191 pair items
        int k = i >> 6, h2 = i & 63;
        int hg = h2 * 2;
        float v0 = Wp[e * 16384 + hg * 128 + k];
        float v1 = Wp[e * 16384 + (hg + 1) * 128 + k];
        uint32_t off = (uint32_t)k * 256 + (((uint32_t)hg * 2) ^ ((k & 7) * 16));
        uint32_t base = 1048576u + (uint32_t)e * 65536u;
        *(uint32_t*)(img + base + off)          = packbf(v0, v1);
        *(uint32_t*)(img + base + 32768u + off) = packbf(blo(v0), blo(v1));
    }
}

__global__ void __launch_bounds__(256) k_gate(const float* __restrict__ feat,
                                              const float* __restrict__ Wg,
                                              float* __restrict__ out) {
    __shared__ float WgT[Ev * 256];
    for (int i = threadIdx.x; i < Dv * Ev; i += 256)
        WgT[(i & 7) * 256 + (i >> 3)] = Wg[i];
    __syncthreads();
    int l = threadIdx.x & 31;
    int tok = blockIdx.x * 8 + (threadIdx.x >> 5);
    if (l == 0) out[tok] = 0.f;
    const float* x = feat + (size_t)tok * Dv;
    float acc[Ev];
#pragma unroll
    for (int e = 0; e < Ev; e++) acc[e] = 0.f;
#pragma unroll
    for (int d0 = 0; d0 < Dv; d0 += 128) {
        float4 x4 = *(const float4*)(x + d0 + l * 4);
#pragma unroll
        for (int e = 0; e < Ev; e++) {
            const float* wr = WgT + e * 256 + d0 + l * 4;
            acc[e] += x4.x * wr[0] + x4.y * wr[1] + x4.z * wr[2] + x4.w * wr[3];
        }
    }
#pragma unroll
    for (int e = 0; e < Ev; e++)
#pragma unroll
        for (int off = 16; off; off >>= 1)
            acc[e] += __shfl_down_sync(0xffffffffu, acc[e], off);
    if (l == 0) {
        float m = acc[0];
#pragma unroll
        for (int e = 1; e < Ev; e++) m = fmaxf(m, acc[e]);
        float g[Ev], sum = 0.f;
#pragma unroll
        for (int e = 0; e < Ev; e++) { g[e] = expf(acc[e] - m); sum += g[e]; }
        float inv = 1.f / sum;
#pragma unroll
        for (int e = 0; e < Ev; e++) g[e] *= inv;
        int i0 = 0;
#pragma unroll
        for (int e = 1; e < Ev; e++) if (g[e] > g[i0]) i0 = e;
        int i1 = -1;
#pragma unroll
        for (int e = 0; e < Ev; e++) {
            if (e == i0) continue;
            if (i1 < 0 || g[e] > g[i1]) i1 = e;
        }
        float denom = g[i0] + g[i1] + 1e-10f;
        int r0 = atomicAdd(&g_count[i0], 1);
        g_tok[i0][r0] = tok; g_w[i0][r0] = g[i0] / denom;
        int r1 = atomicAdd(&g_count[i1], 1);
        g_tok[i1][r1] = tok; g_w[i1][r1] = g[i1] / denom;
    }
}

// smem map (bytes):
//   BUF 0..131072:   GEMM1: A_q hi 0 (32K), A_q lo 32768 (32K), W1q hi 65536
//                    (16K), W1q lo 81920 (16K).  GEMM2: core hi 0 (64K),
//                    core lo 65536 (64K).
//   Wp hi 131072 (32K), Wp lo 163840 (32K),
//   tk 196608 (1K), wt 197632 (1K), b1 198656, bp 199168, Wo 199680 -> 200192
#define OFF_ALO 32768
#define OFF_WH  65536
#define OFF_WL  81920
#define OFF_CLO 65536
#define OFF_PH  131072
#define OFF_PL  163840
#define SMEM_BYTES 200192

__global__ void __launch_bounds__(TPB, 1) k_expert(
    const float* __restrict__ feat,
    const float* __restrict__ b1g, const float* __restrict__ bpg,
    const float* __restrict__ mix_logit,
    const float* __restrict__ Wog, const float* __restrict__ bog,
    float* __restrict__ out)
{
    extern __shared__ __align__(1024) char smb[];
    int*   tk   = (int*)(smb + 196608);
    float* wt   = (float*)(smb + 197632);
    float* b1_s = (float*)(smb + 198656);
    float* bp_s = (float*)(smb + 199168);
    float* Wo_s = (float*)(smb + 199680);

    const int e    = blockIdx.x & 7;
    const int j    = blockIdx.x >> 3;
    const int tid  = threadIdx.x;
    const int warp = tid >> 5;
    const int lane = tid & 31;
    const int mw   = warp & 7;     // M group: 32 tokens (two 16-row strips)
    const int nh   = warp >> 3;    // N half: 64 cols
    const int li   = lane & 3;
    const int lg   = lane >> 2;
    const uint32_t sb = smem_u32(smb);

    // stage Wp (resident) + biases
    {
        const uint4* s = g_img4 + 65536 + (size_t)e * 4096;
        uint4* dH = (uint4*)(smb + OFF_PH);
        uint4* dL = (uint4*)(smb + OFF_PL);
        for (int u = tid; u < 2048; u += TPB) { dH[u] = s[u]; dL[u] = s[u + 2048]; }
    }
    if (tid < 128) {
        b1_s[tid] = b1g[e * 128 + tid];
        bp_s[tid] = bpg[e * 128 + tid];
        Wo_s[tid] = Wog[e * 128 + tid];
    }
    const float mix  = 1.f / (1.f + expf(-mix_logit[e]));
    const float omix = 1.f - mix;
    const float boe  = (nh == 0) ? bog[e] : 0.f;
    const int   n    = g_count[e];

    // fragment addressing (XOR swizzle: kbyte ^ ((row&7)*16))
    const int matA = lane >> 3;
    const uint32_t a_koff = (uint32_t)(matA >> 1) * 16;
    const uint32_t sw     = (uint32_t)(lane & 7) * 16;
    const uint32_t arow0  = (uint32_t)(mw * 32 + (matA & 1) * 8 + (lane & 7));
    const int jt = matA >> 1, kc = matA & 1;
    const uint32_t brow0  = (uint32_t)(nh * 64 + jt * 8 + (lane & 7)); // +ntp*16
    const uint32_t b_koff = (uint32_t)kc * 16;

    for (int tile = j; tile * MT < n; tile += NBv) {
        const int base = tile * MT;
        __syncthreads();               // Wp staged / prev-tile reads done
        if (tid < 256) {
            int idx = min(base + tid, n - 1);
            tk[tid] = g_tok[e][idx];
            wt[tid] = g_w[e][idx];
        }

        float D1[2][8][4];
#pragma unroll
        for (int s = 0; s < 2; s++)
#pragma unroll
            for (int t = 0; t < 8; t++)
#pragma unroll
                for (int q = 0; q < 4; q++) D1[s][t][q] = 0.f;

        // ===== GEMM1 over 4 K-quarters (A rows 128B, 3-pass bf16) =====
        for (int q = 0; q < 4; q++) {
            __syncthreads();           // tk ready / prev quarter reads done
            for (int u = tid; u < 4096; u += TPB) {    // A quarter gather+split
                int ts = u >> 4, c16 = u & 15;
                float4 x4 = *(const float4*)(feat + (size_t)tk[ts] * Dv
                                             + q * 64 + c16 * 4);
                uint32_t off = (uint32_t)ts * 128
                             + (((uint32_t)c16 * 8) ^ ((ts & 7) * 16));
                *(uint2*)(smb + off) =
                    make_uint2(packbf(x4.x, x4.y), packbf(x4.z, x4.w));
                *(uint2*)(smb + OFF_ALO + off) =
                    make_uint2(packbf(blo(x4.x), blo(x4.y)),
                               packbf(blo(x4.z), blo(x4.w)));
            }
            {   // W1 quarter images (pre-swizzled, 128B rows)
                const uint4* s = g_img4 + (size_t)((e * 4 + q) * 2) * 1024;
                uint4* dH = (uint4*)(smb + OFF_WH);
                uint4* dL = (uint4*)(smb + OFF_WL);
                for (int u = tid; u < 1024; u += TPB) {
                    dH[u] = s[u]; dL[u] = s[u + 1024];
                }
            }
            __syncthreads();

            for (int ks = 0; ks < 4; ks++) {
                uint32_t kx  = (uint32_t)ks * 32;
                uint32_t akx = (kx + a_koff) ^ sw;
                uint32_t ah0[4], al0[4], ah1[4], al1[4];
                ldsm4(sb + arow0 * 128 + akx, ah0);
                ldsm4(sb + OFF_ALO + arow0 * 128 + akx, al0);
                ldsm4(sb + (arow0 + 16) * 128 + akx, ah1);
                ldsm4(sb + OFF_ALO + (arow0 + 16) * 128 + akx, al1);
#pragma unroll
                for (int ntp = 0; ntp < 4; ntp++) {
                    uint32_t bkx = ((kx + b_koff) ^ sw)
                                 + (brow0 + ntp * 16) * 128;
                    uint32_t bh[4], bl[4];
                    ldsm4(sb + OFF_WH + bkx, bh);
                    ldsm4(sb + OFF_WL + bkx, bl);
                    mma_bf(D1[0][2 * ntp],     ah0, bh[0], bh[1]);
                    mma_bf(D1[0][2 * ntp + 1], ah0, bh[2], bh[3]);
                    mma_bf(D1[1][2 * ntp],     ah1, bh[0], bh[1]);
                    mma_bf(D1[1][2 * ntp + 1], ah1, bh[2], bh[3]);
                    mma_bf(D1[0][2 * ntp],     ah0, bl[0], bl[1]);
                    mma_bf(D1[0][2 * ntp + 1], ah0, bl[2], bl[3]);
                    mma_bf(D1[1][2 * ntp],     ah1, bl[0], bl[1]);
                    mma_bf(D1[1][2 * ntp + 1], ah1, bl[2], bl[3]);
                    mma_bf(D1[0][2 * ntp],     al0, bh[0], bh[1]);
                    mma_bf(D1[0][2 * ntp + 1], al0, bh[2], bh[3]);
                    mma_bf(D1[1][2 * ntp],     al1, bh[0], bh[1]);
                    mma_bf(D1[1][2 * ntp + 1], al1, bh[2], bh[3]);
                }
            }
        }

        // ===== epilogue 1: relu+b1; Wo partial; core -> smem (256B rows) =====
        __syncthreads();               // GEMM1 reads done -> BUF becomes core
        float s1[2][2];
#pragma unroll
        for (int s = 0; s < 2; s++) {
            const int tok0 = mw * 32 + s * 16 + lg;
            const uint32_t sw0 = (uint32_t)(tok0 & 7) * 16;
            const uint32_t sw1 = (uint32_t)((tok0 + 8) & 7) * 16;
            float a = 0.f, b = 0.f;
#pragma unroll
            for (int t = 0; t < 8; t++) {
                int h0 = nh * 64 + (t >> 1) * 16 + (t & 1) * 8 + li * 2;
                float2 b1v = *(float2*)(b1_s + h0);
                float2 wov = *(float2*)(Wo_s + h0);
                float c0 = fmaxf(D1[s][t][0] + b1v.x, 0.f);
                float c1 = fmaxf(D1[s][t][1] + b1v.y, 0.f);
                float c2 = fmaxf(D1[s][t][2] + b1v.x, 0.f);
                float c3 = fmaxf(D1[s][t][3] + b1v.y, 0.f);
                a += c0 * wov.x + c1 * wov.y;
                b += c2 * wov.x + c3 * wov.y;
                uint32_t col = (uint32_t)h0 * 2;
                uint32_t o0 = (uint32_t)tok0 * 256 + (col ^ sw0);
                uint32_t o1 = (uint32_t)(tok0 + 8) * 256 + (col ^ sw1);
                *(uint32_t*)(smb + o0)           = packbf(c0, c1);
                *(uint32_t*)(smb + OFF_CLO + o0) = packbf(blo(c0), blo(c1));
                *(uint32_t*)(smb + o1)           = packbf(c2, c3);
                *(uint32_t*)(smb + OFF_CLO + o1) = packbf(blo(c2), blo(c3));
            }
            s1[s][0] = a; s1[s][1] = b;
        }
        __syncthreads();

        // ===== GEMM2: D2 = core @ Wp (core 256B rows, Wp resident) =====
        float D2[2][8][4];
#pragma unroll
        for (int s = 0; s < 2; s++)
#pragma unroll
            for (int t = 0; t < 8; t++)
#pragma unroll
                for (int q = 0; q < 4; q++) D2[s][t][q] = 0.f;
        for (int ks = 0; ks < 8; ks++) {
            uint32_t kx  = (uint32_t)ks * 32;
            uint32_t akx = (kx + a_koff) ^ sw;
            uint32_t ah0[4], al0[4], ah1[4], al1[4];
            ldsm4(sb + arow0 * 256 + akx, ah0);
            ldsm4(sb + OFF_CLO + arow0 * 256 + akx, al0);
            ldsm4(sb + (arow0 + 16) * 256 + akx, ah1);
            ldsm4(sb + OFF_CLO + (arow0 + 16) * 256 + akx, al1);
#pragma unroll
            for (int ntp = 0; ntp < 4; ntp++) {
                uint32_t bkx = ((kx + b_koff) ^ sw) + (brow0 + ntp * 16) * 256;
                uint32_t bh[4], bl[4];
                ldsm4(sb + OFF_PH + bkx, bh);
                ldsm4(sb + OFF_PL + bkx, bl);
                mma_bf(D2[0][2 * ntp],     ah0, bh[0], bh[1]);
                mma_bf(D2[0][2 * ntp + 1], ah0, bh[2], bh[3]);
                mma_bf(D2[1][2 * ntp],     ah1, bh[0], bh[1]);
                mma_bf(D2[1][2 * ntp + 1], ah1, bh[2], bh[3]);
                mma_bf(D2[0][2 * ntp],     ah0, bl[0], bl[1]);
                mma_bf(D2[0][2 * ntp + 1], ah0, bl[2], bl[3]);
                mma_bf(D2[1][2 * ntp],     ah1, bl[0], bl[1]);
                mma_bf(D2[1][2 * ntp + 1], ah1, bl[2], bl[3]);
                mma_bf(D2[0][2 * ntp],     al0, bh[0], bh[1]);
                mma_bf(D2[0][2 * ntp + 1], al0, bh[2], bh[3]);
                mma_bf(D2[1][2 * ntp],     al1, bh[0], bh[1]);
                mma_bf(D2[1][2 * ntp + 1], al1, bh[2], bh[3]);
            }
        }

        // ===== epilogue 2: tanh + mix + Wo dot + quad-reduce + atomicAdd =====
#pragma unroll
        for (int s = 0; s < 2; s++) {
            float pa = 0.f, pb = 0.f;
#pragma unroll
            for (int t = 0; t < 8; t++) {
                int k0 = nh * 64 + (t >> 1) * 16 + (t & 1) * 8 + li * 2;
                float2 bpv = *(float2*)(bp_s + k0);
                float2 wov = *(float2*)(Wo_s + k0);
                pa += tanhf(D2[s][t][0] + bpv.x) * wov.x
                    + tanhf(D2[s][t][1] + bpv.y) * wov.y;
                pb += tanhf(D2[s][t][2] + bpv.x) * wov.x
                    + tanhf(D2[s][t][3] + bpv.y) * wov.y;
            }
            float va = omix * s1[s][0] + mix * pa + boe;
            float vb = omix * s1[s][1] + mix * pb + boe;
            va += __shfl_xor_sync(0xffffffffu, va, 1);
            va += __shfl_xor_sync(0xffffffffu, va, 2);
            vb += __shfl_xor_sync(0xffffffffu, vb, 1);
            vb += __shfl_xor_sync(0xffffffffu, vb, 2);
            if (li == 0) {
                int mr = mw * 32 + s * 16 + lg;
                float corr = 3.f * boe;   // boe added by all 4 quad lanes
                if (base + mr < n)
                    atomicAdd(&out[tk[mr]], wt[mr] * (va - corr));
                if (base + mr + 8 < n)
                    atomicAdd(&out[tk[mr + 8]], wt[mr + 8] * (vb - corr));
            }
        }
    }
}

extern "C" void kernel_launch(void* const* d_in, const int* in_sizes, int n_in,
                              void* d_out, int out_size) {
    const float* feat      = (const float*)d_in[0];
    const float* Wg        = (const float*)d_in[1];
    const float* W1        = (const float*)d_in[2];
    const float* b1        = (const float*)d_in[3];
    const float* Wp        = (const float*)d_in[4];
    const float* bp        = (const float*)d_in[5];
    const float* mix_logit = (const float*)d_in[6];
    const float* Wo        = (const float*)d_in[7];
    const float* bo        = (const float*)d_in[8];
    float* out = (float*)d_out;

    cudaFuncSetAttribute(k_expert, cudaFuncAttributeMaxDynamicSharedMemorySize,
                         SMEM_BYTES);
    k_prep<<<Ev * 16, 256>>>(W1, Wp);
    k_gate<<<Bv / 8, 256>>>(feat, Wg, out);
    k_expert<<<NBv * Ev, TPB, SMEM_BYTES>>>(feat, b1, bp, mix_logit, Wo, bo, out);
}

// round 12
// speedup vs baseline: 2.7859x; 1.1546x over previous
#include <cuda_runtime.h>
#include <cuda_fp16.h>
#include <math.h>
#include <stdint.h>

#define Bv 16384
#define Dv 256
#define Ev 8
#define NBv 17          // blocks per expert -> 136 blocks, one wave
#define MT 256          // tokens per tile (ONE tile per block)
#define TPB 512

__device__ int   g_count[Ev];
__device__ int   g_tok[Ev][Bv];
__device__ float g_w[Ev][Bv];
// fp16 images: W1 [e][quarter(4)][hi/lo] 16KB each (1MB), Wp [e][hi/lo] 32KB (0.5MB)
__device__ uint4 g_img4[1572864 / 16];

__device__ __forceinline__ uint32_t smem_u32(const void* p) {
    uint32_t a;
    asm("{ .reg .u64 t; cvta.to.shared.u64 t, %1; cvt.u32.u64 %0, t; }"
        : "=r"(a) : "l"(p));
    return a;
}
__device__ __forceinline__ uint32_t packhf(float even, float odd) {
    uint32_t r;
    asm("cvt.rn.f16x2.f32 %0, %1, %2;" : "=r"(r) : "f"(odd), "f"(even));
    return r;
}
__device__ __forceinline__ float hlo(float v) {
    return v - __half2float(__float2half_rn(v));
}
__device__ __forceinline__ void ldsm4(uint32_t addr, uint32_t* r) {
    asm volatile("ldmatrix.sync.aligned.m8n8.x4.shared.b16 {%0,%1,%2,%3}, [%4];"
        : "=r"(r[0]), "=r"(r[1]), "=r"(r[2]), "=r"(r[3]) : "r"(addr));
}
__device__ __forceinline__ void mma_hf(float* d, const uint32_t* a,
                                       uint32_t b0, uint32_t b1) {
    asm volatile("mma.sync.aligned.m16n8k16.row.col.f32.f16.f16.f32 "
        "{%0,%1,%2,%3}, {%4,%5,%6,%7}, {%8,%9}, {%0,%1,%2,%3};"
        : "+f"(d[0]), "+f"(d[1]), "+f"(d[2]), "+f"(d[3])
        : "r"(a[0]), "r"(a[1]), "r"(a[2]), "r"(a[3]), "r"(b0), "r"(b1));
}

// ---- k_prep: fp16 quarter-blocked W1 image + Wp image + counter zero ----
__global__ void __launch_bounds__(256) k_prep(const float* __restrict__ W1,
                                              const float* __restrict__ Wp) {
    const int e = blockIdx.x >> 4;
    const int p = blockIdx.x & 15;
    unsigned char* img = (unsigned char*)g_img4;
    if (blockIdx.x == 0 && threadIdx.x < Ev) g_count[threadIdx.x] = 0;

    // W1[e][d][h] -> quarter q=d>>6 image: row h (128B), col dl=d&63
    for (int qq = 0; qq < 4; qq++) {
        int i = (p * 4 + qq) * 256 + threadIdx.x;
        int h = i >> 7, d2 = i & 127;
        int dg = d2 * 2;
        float v0 = W1[e * 32768 + dg * 128 + h];
        float v1 = W1[e * 32768 + (dg + 1) * 128 + h];
        int quarter = dg >> 6, dl = dg & 63;
        uint32_t off = (uint32_t)h * 128 + (((uint32_t)dl * 2) ^ ((h & 7) * 16));
        uint32_t hb = (uint32_t)((e * 4 + quarter) * 2) * 16384u;
        *(uint32_t*)(img + hb + off)          = packhf(v0, v1);
        *(uint32_t*)(img + hb + 16384u + off) = packhf(hlo(v0), hlo(v1));
    }
    // Wp[e][h][k] -> row k (256B), col h
    for (int qq = 0; qq < 2; qq++) {
        int i = (p * 2 + qq) * 256 + threadIdx.x;
        int k = i >> 6, h2 = i & 63;
        int hg = h2 * 2;
        float v0 = Wp[e * 16384 + hg * 128 + k];
        float v1 = Wp[e * 16384 + (hg + 1) * 128 + k];
        uint32_t off = (uint32_t)k * 256 + (((uint32_t)hg * 2) ^ ((k & 7) * 16));
        uint32_t base = 1048576u + (uint32_t)e * 65536u;
        *(uint32_t*)(img + base + off)          = packhf(v0, v1);
        *(uint32_t*)(img + base + 32768u + off) = packhf(hlo(v0), hlo(v1));
    }
}

__global__ void __launch_bounds__(256) k_gate(const float* __restrict__ feat,
                                              const float* __restrict__ Wg,
                                              float* __restrict__ out) {
    __shared__ float WgT[Ev * 256];
    for (int i = threadIdx.x; i < Dv * Ev; i += 256)
        WgT[(i & 7) * 256 + (i >> 3)] = Wg[i];
    __syncthreads();
    int l = threadIdx.x & 31;
    int tok = blockIdx.x * 8 + (threadIdx.x >> 5);
    if (l == 0) out[tok] = 0.f;
    const float* x = feat + (size_t)tok * Dv;
    float acc[Ev];
#pragma unroll
    for (int e = 0; e < Ev; e++) acc[e] = 0.f;
#pragma unroll
    for (int d0 = 0; d0 < Dv; d0 += 128) {
        float4 x4 = *(const float4*)(x + d0 + l * 4);
#pragma unroll
        for (int e = 0; e < Ev; e++) {
            const float* wr = WgT + e * 256 + d0 + l * 4;
            acc[e] += x4.x * wr[0] + x4.y * wr[1] + x4.z * wr[2] + x4.w * wr[3];
        }
    }
#pragma unroll
    for (int e = 0; e < Ev; e++)
#pragma unroll
        for (int off = 16; off; off >>= 1)
            acc[e] += __shfl_down_sync(0xffffffffu, acc[e], off);
    if (l == 0) {
        float m = acc[0];
#pragma unroll
        for (int e = 1; e < Ev; e++) m = fmaxf(m, acc[e]);
        float g[Ev], sum = 0.f;
#pragma unroll
        for (int e = 0; e < Ev; e++) { g[e] = expf(acc[e] - m); sum += g[e]; }
        float inv = 1.f / sum;
#pragma unroll
        for (int e = 0; e < Ev; e++) g[e] *= inv;
        int i0 = 0;
#pragma unroll
        for (int e = 1; e < Ev; e++) if (g[e] > g[i0]) i0 = e;
        int i1 = -1;
#pragma unroll
        for (int e = 0; e < Ev; e++) {
            if (e == i0) continue;
            if (i1 < 0 || g[e] > g[i1]) i1 = e;
        }
        float denom = g[i0] + g[i1] + 1e-10f;
        int r0 = atomicAdd(&g_count[i0], 1);
        g_tok[i0][r0] = tok; g_w[i0][r0] = g[i0] / denom;
        int r1 = atomicAdd(&g_count[i1], 1);
        g_tok[i1][r1] = tok; g_w[i1][r1] = g[i1] / denom;
    }
}

// smem map (bytes):
//   BUF 0..65536: GEMM1: A_hi 0 (32K), W1q hi 32768 (16K), W1q lo 49152 (16K)
//                 GEMM2: core_hi 0..65536 (256 rows x 256B)
//   Wp hi 65536 (32K), Wp lo 98304 (32K),
//   tk 131072 (1K), wt 132096 (1K), b1 133120, bp 133632, Wo 134144 -> 134656
#define OFF_WH  32768
#define OFF_WL  49152
#define OFF_PH  65536
#define OFF_PL  98304
#define SMEM_BYTES 134656

__global__ void __launch_bounds__(TPB, 1) k_expert(
    const float* __restrict__ feat,
    const float* __restrict__ b1g, const float* __restrict__ bpg,
    const float* __restrict__ mix_logit,
    const float* __restrict__ Wog, const float* __restrict__ bog,
    float* __restrict__ out)
{
    extern __shared__ __align__(1024) char smb[];
    int*   tk   = (int*)(smb + 131072);
    float* wt   = (float*)(smb + 132096);
    float* b1_s = (float*)(smb + 133120);
    float* bp_s = (float*)(smb + 133632);
    float* Wo_s = (float*)(smb + 134144);

    const int e    = blockIdx.x & 7;
    const int j    = blockIdx.x >> 3;
    const int tid  = threadIdx.x;
    const int warp = tid >> 5;
    const int lane = tid & 31;
    const int mw   = warp & 7;     // M group: 32 tokens (two 16-row strips)
    const int nh   = warp >> 3;    // N half: 64 cols
    const int li   = lane & 3;
    const int lg   = lane >> 2;
    const uint32_t sb = smem_u32(smb);

    // stage Wp (resident) + biases
    {
        const uint4* s = g_img4 + 65536 + (size_t)e * 4096;
        uint4* dH = (uint4*)(smb + OFF_PH);
        uint4* dL = (uint4*)(smb + OFF_PL);
        for (int u = tid; u < 2048; u += TPB) { dH[u] = s[u]; dL[u] = s[u + 2048]; }
    }
    if (tid < 128) {
        b1_s[tid] = b1g[e * 128 + tid];
        bp_s[tid] = bpg[e * 128 + tid];
        Wo_s[tid] = Wog[e * 128 + tid];
    }
    const float mix  = 1.f / (1.f + expf(-mix_logit[e]));
    const float omix = 1.f - mix;
    const float boe  = (nh == 0) ? bog[e] : 0.f;
    const int   n    = g_count[e];

    // fragment addressing (XOR swizzle: kbyte ^ ((row&7)*16))
    const int matA = lane >> 3;
    const uint32_t a_koff = (uint32_t)(matA >> 1) * 16;
    const uint32_t sw     = (uint32_t)(lane & 7) * 16;
    const uint32_t arow0  = (uint32_t)(mw * 32 + (matA & 1) * 8 + (lane & 7));
    const int jt = matA >> 1, kc = matA & 1;
    const uint32_t brow0  = (uint32_t)(nh * 64 + jt * 8 + (lane & 7)); // +ntp*16
    const uint32_t b_koff = (uint32_t)kc * 16;

    for (int tile = j; tile * MT < n; tile += NBv) {
        const int base = tile * MT;
        __syncthreads();               // Wp staged / prev-tile reads done
        if (tid < 256) {
            int idx = min(base + tid, n - 1);
            tk[tid] = g_tok[e][idx];
            wt[tid] = g_w[e][idx];
        }

        float D1[2][8][4];
#pragma unroll
        for (int s = 0; s < 2; s++)
#pragma unroll
            for (int t = 0; t < 8; t++)
#pragma unroll
                for (int q = 0; q < 4; q++) D1[s][t][q] = 0.f;

        // ===== GEMM1 over 4 K-quarters: D1 = Ah*(W1h + W1l) =====
        for (int q = 0; q < 4; q++) {
            __syncthreads();           // tk ready / prev quarter reads done
            for (int u = tid; u < 4096; u += TPB) {    // A quarter gather (hi only)
                int ts = u >> 4, c16 = u & 15;
                float4 x4 = *(const float4*)(feat + (size_t)tk[ts] * Dv
                                             + q * 64 + c16 * 4);
                uint32_t off = (uint32_t)ts * 128
                             + (((uint32_t)c16 * 8) ^ ((ts & 7) * 16));
                *(uint2*)(smb + off) =
                    make_uint2(packhf(x4.x, x4.y), packhf(x4.z, x4.w));
            }
            {   // W1 quarter images (pre-swizzled fp16, 128B rows)
                const uint4* s = g_img4 + (size_t)((e * 4 + q) * 2) * 1024;
                uint4* dH = (uint4*)(smb + OFF_WH);
                uint4* dL = (uint4*)(smb + OFF_WL);
                for (int u = tid; u < 1024; u += TPB) {
                    dH[u] = s[u]; dL[u] = s[u + 1024];
                }
            }
            __syncthreads();

            for (int ks = 0; ks < 4; ks++) {
                uint32_t kx  = (uint32_t)ks * 32;
                uint32_t akx = (kx + a_koff) ^ sw;
                uint32_t ah0[4], ah1[4];
                ldsm4(sb + arow0 * 128 + akx, ah0);
                ldsm4(sb + (arow0 + 16) * 128 + akx, ah1);
#pragma unroll
                for (int ntp = 0; ntp < 4; ntp++) {
                    uint32_t bkx = ((kx + b_koff) ^ sw)
                                 + (brow0 + ntp * 16) * 128;
                    uint32_t bh[4], bl[4];
                    ldsm4(sb + OFF_WH + bkx, bh);
                    ldsm4(sb + OFF_WL + bkx, bl);
                    mma_hf(D1[0][2 * ntp],     ah0, bh[0], bh[1]);
                    mma_hf(D1[0][2 * ntp + 1], ah0, bh[2], bh[3]);
                    mma_hf(D1[1][2 * ntp],     ah1, bh[0], bh[1]);
                    mma_hf(D1[1][2 * ntp + 1], ah1, bh[2], bh[3]);
                    mma_hf(D1[0][2 * ntp],     ah0, bl[0], bl[1]);
                    mma_hf(D1[0][2 * ntp + 1], ah0, bl[2], bl[3]);
                    mma_hf(D1[1][2 * ntp],     ah1, bl[0], bl[1]);
                    mma_hf(D1[1][2 * ntp + 1], ah1, bl[2], bl[3]);
                }
            }
        }

        // ===== epilogue 1: relu+b1; Wo partial; core(hi fp16) -> smem =====
        __syncthreads();               // GEMM1 reads done -> BUF becomes core
        float s1[2][2];
#pragma unroll
        for (int s = 0; s < 2; s++) {
            const int tok0 = mw * 32 + s * 16 + lg;
            const uint32_t sw0 = (uint32_t)(tok0 & 7) * 16;
            const uint32_t sw1 = (uint32_t)((tok0 + 8) & 7) * 16;
            float a = 0.f, b = 0.f;
#pragma unroll
            for (int t = 0; t < 8; t++) {
                int h0 = nh * 64 + (t >> 1) * 16 + (t & 1) * 8 + li * 2;
                float2 b1v = *(float2*)(b1_s + h0);
                float2 wov = *(float2*)(Wo_s + h0);
                float c0 = fmaxf(D1[s][t][0] + b1v.x, 0.f);
                float c1 = fmaxf(D1[s][t][1] + b1v.y, 0.f);
                float c2 = fmaxf(D1[s][t][2] + b1v.x, 0.f);
                float c3 = fmaxf(D1[s][t][3] + b1v.y, 0.f);
                a += c0 * wov.x + c1 * wov.y;
                b += c2 * wov.x + c3 * wov.y;
                uint32_t col = (uint32_t)h0 * 2;
                uint32_t o0 = (uint32_t)tok0 * 256 + (col ^ sw0);
                uint32_t o1 = (uint32_t)(tok0 + 8) * 256 + (col ^ sw1);
                *(uint32_t*)(smb + o0) = packhf(c0, c1);
                *(uint32_t*)(smb + o1) = packhf(c2, c3);
            }
            s1[s][0] = a; s1[s][1] = b;
        }
        __syncthreads();

        // ===== GEMM2: D2 = core_h @ (Wp_h + Wp_l) =====
        float D2[2][8][4];
#pragma unroll
        for (int s = 0; s < 2; s++)
#pragma unroll
            for (int t = 0; t < 8; t++)
#pragma unroll
                for (int q = 0; q < 4; q++) D2[s][t][q] = 0.f;
        for (int ks = 0; ks < 8; ks++) {
            uint32_t kx  = (uint32_t)ks * 32;
            uint32_t akx = (kx + a_koff) ^ sw;
            uint32_t ah0[4], ah1[4];
            ldsm4(sb + arow0 * 256 + akx, ah0);
            ldsm4(sb + (arow0 + 16) * 256 + akx, ah1);
#pragma unroll
            for (int ntp = 0; ntp < 4; ntp++) {
                uint32_t bkx = ((kx + b_koff) ^ sw) + (brow0 + ntp * 16) * 256;
                uint32_t bh[4], bl[4];
                ldsm4(sb + OFF_PH + bkx, bh);
                ldsm4(sb + OFF_PL + bkx, bl);
                mma_hf(D2[0][2 * ntp],     ah0, bh[0], bh[1]);
                mma_hf(D2[0][2 * ntp + 1], ah0, bh[2], bh[3]);
                mma_hf(D2[1][2 * ntp],     ah1, bh[0], bh[1]);
                mma_hf(D2[1][2 * ntp + 1], ah1, bh[2], bh[3]);
                mma_hf(D2[0][2 * ntp],     ah0, bl[0], bl[1]);
                mma_hf(D2[0][2 * ntp + 1], ah0, bl[2], bl[3]);
                mma_hf(D2[1][2 * ntp],     ah1, bl[0], bl[1]);
                mma_hf(D2[1][2 * ntp + 1], ah1, bl[2], bl[3]);
            }
        }

        // ===== epilogue 2: tanh + mix + Wo dot + quad-reduce + atomicAdd =====
#pragma unroll
        for (int s = 0; s < 2; s++) {
            float pa = 0.f, pb = 0.f;
#pragma unroll
            for (int t = 0; t < 8; t++) {
                int k0 = nh * 64 + (t >> 1) * 16 + (t & 1) * 8 + li * 2;
                float2 bpv = *(float2*)(bp_s + k0);
                float2 wov = *(float2*)(Wo_s + k0);
                pa += tanhf(D2[s][t][0] + bpv.x) * wov.x
                    + tanhf(D2[s][t][1] + bpv.y) * wov.y;
                pb += tanhf(D2[s][t][2] + bpv.x) * wov.x
                    + tanhf(D2[s][t][3] + bpv.y) * wov.y;
            }
            float va = omix * s1[s][0] + mix * pa + boe;
            float vb = omix * s1[s][1] + mix * pb + boe;
            va += __shfl_xor_sync(0xffffffffu, va, 1);
            va += __shfl_xor_sync(0xffffffffu, va, 2);
            vb += __shfl_xor_sync(0xffffffffu, vb, 1);
            vb += __shfl_xor_sync(0xffffffffu, vb, 2);
            if (li == 0) {
                int mr = mw * 32 + s * 16 + lg;
                float corr = 3.f * boe;   // boe added by all 4 quad lanes
                if (base + mr < n)
                    atomicAdd(&out[tk[mr]], wt[mr] * (va - corr));
                if (base + mr + 8 < n)
                    atomicAdd(&out[tk[mr + 8]], wt[mr + 8] * (vb - corr));
            }
        }
    }
}

extern "C" void kernel_launch(void* const* d_in, const int* in_sizes, int n_in,
                              void* d_out, int out_size) {
    const float* feat      = (const float*)d_in[0];
    const float* Wg        = (const float*)d_in[1];
    const float* W1        = (const float*)d_in[2];
    const float* b1        = (const float*)d_in[3];
    const float* Wp        = (const float*)d_in[4];
    const float* bp        = (const float*)d_in[5];
    const float* mix_logit = (const float*)d_in[6];
    const float* Wo        = (const float*)d_in[7];
    const float* bo        = (const float*)d_in[8];
    float* out = (float*)d_out;

    cudaFuncSetAttribute(k_expert, cudaFuncAttributeMaxDynamicSharedMemorySize,
                         SMEM_BYTES);
    k_prep<<<Ev * 16, 256>>>(W1, Wp);
    k_gate<<<Bv / 8, 256>>>(feat, Wg, out);
    k_expert<<<NBv * Ev, TPB, SMEM_BYTES>>>(feat, b1, bp, mix_logit, Wo, bo, out);
}

// round 13
// speedup vs baseline: 3.0887x; 1.1087x over previous
#include <cuda_runtime.h>
#include <cuda_fp16.h>
#include <math.h>
#include <stdint.h>

#define Bv 16384
#define Dv 256
#define Ev 8
#define NBv 17          // blocks per expert -> 136 blocks, one wave
#define MT 256          // tokens per tile (ONE tile per block)
#define TPB 512

__device__ int   g_count[Ev];
__device__ int   g_tok[Ev][Bv];
__device__ float g_w[Ev][Bv];
// fp16 hi images: W1 [e][quarter(4)] 16KB each (512KB), Wp [e] 32KB (256KB)
__device__ uint4 g_img4[1572864 / 16];

__device__ __forceinline__ uint32_t smem_u32(const void* p) {
    uint32_t a;
    asm("{ .reg .u64 t; cvta.to.shared.u64 t, %1; cvt.u32.u64 %0, t; }"
        : "=r"(a) : "l"(p));
    return a;
}
__device__ __forceinline__ uint32_t packhf(float even, float odd) {
    uint32_t r;
    asm("cvt.rn.f16x2.f32 %0, %1, %2;" : "=r"(r) : "f"(odd), "f"(even));
    return r;
}
__device__ __forceinline__ void ldsm4(uint32_t addr, uint32_t* r) {
    asm volatile("ldmatrix.sync.aligned.m8n8.x4.shared.b16 {%0,%1,%2,%3}, [%4];"
        : "=r"(r[0]), "=r"(r[1]), "=r"(r[2]), "=r"(r[3]) : "r"(addr));
}
__device__ __forceinline__ void mma_hf(float* d, const uint32_t* a,
                                       uint32_t b0, uint32_t b1) {
    asm volatile("mma.sync.aligned.m16n8k16.row.col.f32.f16.f16.f32 "
        "{%0,%1,%2,%3}, {%4,%5,%6,%7}, {%8,%9}, {%0,%1,%2,%3};"
        : "+f"(d[0]), "+f"(d[1]), "+f"(d[2]), "+f"(d[3])
        : "r"(a[0]), "r"(a[1]), "r"(a[2]), "r"(a[3]), "r"(b0), "r"(b1));
}

// ---- k_prep: fp16 hi-only weight images + counter zero ----
__global__ void __launch_bounds__(256) k_prep(const float* __restrict__ W1,
                                              const float* __restrict__ Wp) {
    const int e = blockIdx.x >> 4;
    const int p = blockIdx.x & 15;
    unsigned char* img = (unsigned char*)g_img4;
    if (blockIdx.x == 0 && threadIdx.x < Ev) g_count[threadIdx.x] = 0;

    // W1[e][d][h] -> quarter q=d>>6 image: row h (128B), col dl=d&63
    for (int qq = 0; qq < 4; qq++) {
        int i = (p * 4 + qq) * 256 + threadIdx.x;
        int h = i >> 7, d2 = i & 127;
        int dg = d2 * 2;
        float v0 = W1[e * 32768 + dg * 128 + h];
        float v1 = W1[e * 32768 + (dg + 1) * 128 + h];
        int quarter = dg >> 6, dl = dg & 63;
        uint32_t off = (uint32_t)h * 128 + (((uint32_t)dl * 2) ^ ((h & 7) * 16));
        *(uint32_t*)(img + (uint32_t)(e * 4 + quarter) * 16384u + off)
            = packhf(v0, v1);
    }
    // Wp[e][h][k] -> row k (256B), col h
    for (int qq = 0; qq < 2; qq++) {
        int i = (p * 2 + qq) * 256 + threadIdx.x;
        int k = i >> 6, h2 = i & 63;
        int hg = h2 * 2;
        float v0 = Wp[e * 16384 + hg * 128 + k];
        float v1 = Wp[e * 16384 + (hg + 1) * 128 + k];
        uint32_t off = (uint32_t)k * 256 + (((uint32_t)hg * 2) ^ ((k & 7) * 16));
        *(uint32_t*)(img + 524288u + (uint32_t)e * 32768u + off)
            = packhf(v0, v1);
    }
}

__global__ void __launch_bounds__(256) k_gate(const float* __restrict__ feat,
                                              const float* __restrict__ Wg,
                                              float* __restrict__ out) {
    __shared__ float WgT[Ev * 256];
    for (int i = threadIdx.x; i < Dv * Ev; i += 256)
        WgT[(i & 7) * 256 + (i >> 3)] = Wg[i];
    __syncthreads();
    int l = threadIdx.x & 31;
    int tok = blockIdx.x * 8 + (threadIdx.x >> 5);
    if (l == 0) out[tok] = 0.f;
    const float* x = feat + (size_t)tok * Dv;
    float acc[Ev];
#pragma unroll
    for (int e = 0; e < Ev; e++) acc[e] = 0.f;
#pragma unroll
    for (int d0 = 0; d0 < Dv; d0 += 128) {
        float4 x4 = *(const float4*)(x + d0 + l * 4);
#pragma unroll
        for (int e = 0; e < Ev; e++) {
            const float* wr = WgT + e * 256 + d0 + l * 4;
            acc[e] += x4.x * wr[0] + x4.y * wr[1] + x4.z * wr[2] + x4.w * wr[3];
        }
    }
#pragma unroll
    for (int e = 0; e < Ev; e++)
#pragma unroll
        for (int off = 16; off; off >>= 1)
            acc[e] += __shfl_down_sync(0xffffffffu, acc[e], off);
    if (l == 0) {
        float m = acc[0];
#pragma unroll
        for (int e = 1; e < Ev; e++) m = fmaxf(m, acc[e]);
        float g[Ev], sum = 0.f;
#pragma unroll
        for (int e = 0; e < Ev; e++) { g[e] = expf(acc[e] - m); sum += g[e]; }
        float inv = 1.f / sum;
#pragma unroll
        for (int e = 0; e < Ev; e++) g[e] *= inv;
        int i0 = 0;
#pragma unroll
        for (int e = 1; e < Ev; e++) if (g[e] > g[i0]) i0 = e;
        int i1 = -1;
#pragma unroll
        for (int e = 0; e < Ev; e++) {
            if (e == i0) continue;
            if (i1 < 0 || g[e] > g[i1]) i1 = e;
        }
        float denom = g[i0] + g[i1] + 1e-10f;
        int r0 = atomicAdd(&g_count[i0], 1);
        g_tok[i0][r0] = tok; g_w[i0][r0] = g[i0] / denom;
        int r1 = atomicAdd(&g_count[i1], 1);
        g_tok[i1][r1] = tok; g_w[i1][r1] = g[i1] / denom;
    }
}

// smem map (bytes):
//   BUF 0..65536: GEMM1: A_hi 0 (32K), W1q 32768 (16K)
//                 GEMM2: core_hi 0..65536 (256 rows x 256B)
//   Wp 65536 (32K), tk 98304 (1K), wt 99328 (1K),
//   b1 100352, bp 100864, Wo 101376 -> 101888
#define OFF_WH  32768
#define OFF_PH  65536
#define SMEM_BYTES 101888

__global__ void __launch_bounds__(TPB, 1) k_expert(
    const float* __restrict__ feat,
    const float* __restrict__ b1g, const float* __restrict__ bpg,
    const float* __restrict__ mix_logit,
    const float* __restrict__ Wog, const float* __restrict__ bog,
    float* __restrict__ out)
{
    extern __shared__ __align__(1024) char smb[];
    int*   tk   = (int*)(smb + 98304);
    float* wt   = (float*)(smb + 99328);
    float* b1_s = (float*)(smb + 100352);
    float* bp_s = (float*)(smb + 100864);
    float* Wo_s = (float*)(smb + 101376);

    const int e    = blockIdx.x & 7;
    const int j    = blockIdx.x >> 3;
    const int tid  = threadIdx.x;
    const int warp = tid >> 5;
    const int lane = tid & 31;
    const int mw   = warp & 7;     // M group: 32 tokens (two 16-row strips)
    const int nh   = warp >> 3;    // N half: 64 cols
    const int li   = lane & 3;
    const int lg   = lane >> 2;
    const uint32_t sb = smem_u32(smb);

    // stage Wp (resident) + biases
    {
        const uint4* s = g_img4 + 32768 + (size_t)e * 2048;
        uint4* d = (uint4*)(smb + OFF_PH);
        for (int u = tid; u < 2048; u += TPB) d[u] = s[u];
    }
    if (tid < 128) {
        b1_s[tid] = b1g[e * 128 + tid];
        bp_s[tid] = bpg[e * 128 + tid];
        Wo_s[tid] = Wog[e * 128 + tid];
    }
    const float mix  = 1.f / (1.f + expf(-mix_logit[e]));
    const float omix = 1.f - mix;
    const float boe  = (nh == 0) ? bog[e] : 0.f;
    const int   n    = g_count[e];

    // fragment addressing (XOR swizzle: kbyte ^ ((row&7)*16))
    const int matA = lane >> 3;
    const uint32_t a_koff = (uint32_t)(matA >> 1) * 16;
    const uint32_t sw     = (uint32_t)(lane & 7) * 16;
    const uint32_t arow0  = (uint32_t)(mw * 32 + (matA & 1) * 8 + (lane & 7));
    const int jt = matA >> 1, kc = matA & 1;
    const uint32_t brow0  = (uint32_t)(nh * 64 + jt * 8 + (lane & 7)); // +ntp*16
    const uint32_t b_koff = (uint32_t)kc * 16;

    for (int tile = j; tile * MT < n; tile += NBv) {
        const int base = tile * MT;
        __syncthreads();               // Wp staged / prev-tile reads done
        if (tid < 256) {
            int idx = min(base + tid, n - 1);
            tk[tid] = g_tok[e][idx];
            wt[tid] = g_w[e][idx];
        }

        float D1[2][8][4];
#pragma unroll
        for (int s = 0; s < 2; s++)
#pragma unroll
            for (int t = 0; t < 8; t++)
#pragma unroll
                for (int q = 0; q < 4; q++) D1[s][t][q] = 0.f;

        // ===== GEMM1 over 4 K-quarters: D1 = Ah @ W1h (single pass) =====
        for (int q = 0; q < 4; q++) {
            __syncthreads();           // tk ready / prev quarter reads done
            for (int u = tid; u < 4096; u += TPB) {    // A quarter gather
                int ts = u >> 4, c16 = u & 15;
                float4 x4 = *(const float4*)(feat + (size_t)tk[ts] * Dv
                                             + q * 64 + c16 * 4);
                uint32_t off = (uint32_t)ts * 128
                             + (((uint32_t)c16 * 8) ^ ((ts & 7) * 16));
                *(uint2*)(smb + off) =
                    make_uint2(packhf(x4.x, x4.y), packhf(x4.z, x4.w));
            }
            {   // W1 quarter image (pre-swizzled fp16, 128B rows)
                const uint4* s = g_img4 + (size_t)(e * 4 + q) * 1024;
                uint4* d = (uint4*)(smb + OFF_WH);
                for (int u = tid; u < 1024; u += TPB) d[u] = s[u];
            }
            __syncthreads();

            for (int ks = 0; ks < 4; ks++) {
                uint32_t kx  = (uint32_t)ks * 32;
                uint32_t akx = (kx + a_koff) ^ sw;
                uint32_t ah0[4], ah1[4];
                ldsm4(sb + arow0 * 128 + akx, ah0);
                ldsm4(sb + (arow0 + 16) * 128 + akx, ah1);
#pragma unroll
                for (int ntp = 0; ntp < 4; ntp++) {
                    uint32_t bkx = ((kx + b_koff) ^ sw)
                                 + (brow0 + ntp * 16) * 128;
                    uint32_t bh[4];
                    ldsm4(sb + OFF_WH + bkx, bh);
                    mma_hf(D1[0][2 * ntp],     ah0, bh[0], bh[1]);
                    mma_hf(D1[0][2 * ntp + 1], ah0, bh[2], bh[3]);
                    mma_hf(D1[1][2 * ntp],     ah1, bh[0], bh[1]);
                    mma_hf(D1[1][2 * ntp + 1], ah1, bh[2], bh[3]);
                }
            }
        }

        // ===== epilogue 1: relu+b1; Wo partial; core(hi fp16) -> smem =====
        __syncthreads();               // GEMM1 reads done -> BUF becomes core
        float s1[2][2];
#pragma unroll
        for (int s = 0; s < 2; s++) {
            const int tok0 = mw * 32 + s * 16 + lg;
            const uint32_t sw0 = (uint32_t)(tok0 & 7) * 16;
            const uint32_t sw1 = (uint32_t)((tok0 + 8) & 7) * 16;
            float a = 0.f, b = 0.f;
#pragma unroll
            for (int t = 0; t < 8; t++) {
                int h0 = nh * 64 + (t >> 1) * 16 + (t & 1) * 8 + li * 2;
                float2 b1v = *(float2*)(b1_s + h0);
                float2 wov = *(float2*)(Wo_s + h0);
                float c0 = fmaxf(D1[s][t][0] + b1v.x, 0.f);
                float c1 = fmaxf(D1[s][t][1] + b1v.y, 0.f);
                float c2 = fmaxf(D1[s][t][2] + b1v.x, 0.f);
                float c3 = fmaxf(D1[s][t][3] + b1v.y, 0.f);
                a += c0 * wov.x + c1 * wov.y;
                b += c2 * wov.x + c3 * wov.y;
                uint32_t col = (uint32_t)h0 * 2;
                uint32_t o0 = (uint32_t)tok0 * 256 + (col ^ sw0);
                uint32_t o1 = (uint32_t)(tok0 + 8) * 256 + (col ^ sw1);
                *(uint32_t*)(smb + o0) = packhf(c0, c1);
                *(uint32_t*)(smb + o1) = packhf(c2, c3);
            }
            s1[s][0] = a; s1[s][1] = b;
        }
        __syncthreads();

        // ===== GEMM2: D2 = core_h @ Wp_h (single pass) =====
        float D2[2][8][4];
#pragma unroll
        for (int s = 0; s < 2; s++)
#pragma unroll
            for (int t = 0; t < 8; t++)
#pragma unroll
                for (int q = 0; q < 4; q++) D2[s][t][q] = 0.f;
        for (int ks = 0; ks < 8; ks++) {
            uint32_t kx  = (uint32_t)ks * 32;
            uint32_t akx = (kx + a_koff) ^ sw;
            uint32_t ah0[4], ah1[4];
            ldsm4(sb + arow0 * 256 + akx, ah0);
            ldsm4(sb + (arow0 + 16) * 256 + akx, ah1);
#pragma unroll
            for (int ntp = 0; ntp < 4; ntp++) {
                uint32_t bkx = ((kx + b_koff) ^ sw) + (brow0 + ntp * 16) * 256;
                uint32_t bh[4];
                ldsm4(sb + OFF_PH + bkx, bh);
                mma_hf(D2[0][2 * ntp],     ah0, bh[0], bh[1]);
                mma_hf(D2[0][2 * ntp + 1], ah0, bh[2], bh[3]);
                mma_hf(D2[1][2 * ntp],     ah1, bh[0], bh[1]);
                mma_hf(D2[1][2 * ntp + 1], ah1, bh[2], bh[3]);
            }
        }

        // ===== epilogue 2: tanh + mix + Wo dot + quad-reduce + atomicAdd =====
#pragma unroll
        for (int s = 0; s < 2; s++) {
            float pa = 0.f, pb = 0.f;
#pragma unroll
            for (int t = 0; t < 8; t++) {
                int k0 = nh * 64 + (t >> 1) * 16 + (t & 1) * 8 + li * 2;
                float2 bpv = *(float2*)(bp_s + k0);
                float2 wov = *(float2*)(Wo_s + k0);
                pa += tanhf(D2[s][t][0] + bpv.x) * wov.x
                    + tanhf(D2[s][t][1] + bpv.y) * wov.y;
                pb += tanhf(D2[s][t][2] + bpv.x) * wov.x
                    + tanhf(D2[s][t][3] + bpv.y) * wov.y;
            }
            float va = omix * s1[s][0] + mix * pa + boe;
            float vb = omix * s1[s][1] + mix * pb + boe;
            va += __shfl_xor_sync(0xffffffffu, va, 1);
            va += __shfl_xor_sync(0xffffffffu, va, 2);
            vb += __shfl_xor_sync(0xffffffffu, vb, 1);
            vb += __shfl_xor_sync(0xffffffffu, vb, 2);
            if (li == 0) {
                int mr = mw * 32 + s * 16 + lg;
                float corr = 3.f * boe;   // boe added by all 4 quad lanes
                if (base + mr < n)
                    atomicAdd(&out[tk[mr]], wt[mr] * (va - corr));
                if (base + mr + 8 < n)
                    atomicAdd(&out[tk[mr + 8]], wt[mr + 8] * (vb - corr));
            }
        }
    }
}

extern "C" void kernel_launch(void* const* d_in, const int* in_sizes, int n_in,
                              void* d_out, int out_size) {
    const float* feat      = (const float*)d_in[0];
    const float* Wg        = (const float*)d_in[1];
    const float* W1        = (const float*)d_in[2];
    const float* b1        = (const float*)d_in[3];
    const float* Wp        = (const float*)d_in[4];
    const float* bp        = (const float*)d_in[5];
    const float* mix_logit = (const float*)d_in[6];
    const float* Wo        = (const float*)d_in[7];
    const float* bo        = (const float*)d_in[8];
    float* out = (float*)d_out;

    cudaFuncSetAttribute(k_expert, cudaFuncAttributeMaxDynamicSharedMemorySize,
                         SMEM_BYTES);
    k_prep<<<Ev * 16, 256>>>(W1, Wp);
    k_gate<<<Bv / 8, 256>>>(feat, Wg, out);
    k_expert<<<NBv * Ev, TPB, SMEM_BYTES>>>(feat, b1, bp, mix_logit, Wo, bo, out);
}